// round 11
// baseline (speedup 1.0000x reference)
#include <cuda_runtime.h>
#include <cuda_bf16.h>
#include <cstdint>

#define SEQ 2048
#define DIM 64
#define NBH 32   // B*H
#define RS 72    // smem row stride in bf16 (144B, conflict-free ldmatrix)

// Scratch (device globals; no allocs allowed)
__device__ __nv_bfloat16 g_qh[(size_t)NBH * SEQ * DIM];
__device__ __nv_bfloat16 g_ql[(size_t)NBH * SEQ * DIM];
__device__ __nv_bfloat16 g_kh[(size_t)NBH * SEQ * DIM];
__device__ __nv_bfloat16 g_kl[(size_t)NBH * SEQ * DIM];
__device__ __nv_bfloat16 g_vt_hi[(size_t)NBH * DIM * SEQ];
__device__ __nv_bfloat16 g_vt_lo[(size_t)NBH * DIM * SEQ];
__device__ __nv_bfloat16 g_ah[(size_t)NBH * SEQ * SEQ];   // unnormalized exp, hi
__device__ __nv_bfloat16 g_al[(size_t)NBH * SEQ * SEQ];   // unnormalized exp, lo
__device__ float    g_inv[(size_t)NBH * SEQ];
__device__ uint32_t g_mbits[(size_t)SEQ * (SEQ / 32)];

// ---------------- helpers ----------------
__device__ __forceinline__ uint32_t smem_u32(const void* p) {
    uint32_t a;
    asm("{ .reg .u64 t; cvta.to.shared.u64 t, %1; cvt.u32.u64 %0, t; }" : "=r"(a) : "l"(p));
    return a;
}
__device__ __forceinline__ void ldsm_x4(uint32_t r[4], uint32_t addr) {
    asm volatile("ldmatrix.sync.aligned.m8n8.x4.shared.b16 {%0,%1,%2,%3}, [%4];"
        : "=r"(r[0]), "=r"(r[1]), "=r"(r[2]), "=r"(r[3]) : "r"(addr));
}
__device__ __forceinline__ void ldsm_x2(uint32_t r[2], uint32_t addr) {
    asm volatile("ldmatrix.sync.aligned.m8n8.x2.shared.b16 {%0,%1}, [%2];"
        : "=r"(r[0]), "=r"(r[1]) : "r"(addr));
}
__device__ __forceinline__ void mma16816(float c[4], const uint32_t a[4], const uint32_t b[2]) {
    asm volatile(
        "mma.sync.aligned.m16n8k16.row.col.f32.bf16.bf16.f32 "
        "{%0,%1,%2,%3}, {%4,%5,%6,%7}, {%8,%9}, {%0,%1,%2,%3};"
        : "+f"(c[0]), "+f"(c[1]), "+f"(c[2]), "+f"(c[3])
        : "r"(a[0]), "r"(a[1]), "r"(a[2]), "r"(a[3]), "r"(b[0]), "r"(b[1]));
}
__device__ __forceinline__ void cp16(uint32_t dst, const void* src) {
    asm volatile("{ .reg .u64 g; cvta.to.global.u64 g, %1; cp.async.cg.shared.global [%0], [g], 16; }"
        :: "r"(dst), "l"(src) : "memory");
}
#define CP_COMMIT asm volatile("cp.async.commit_group;" ::: "memory")
#define CP_WAIT0  asm volatile("cp.async.wait_group 0;" ::: "memory")

__device__ __forceinline__ void split4(float4 v, uint32_t& h01, uint32_t& h23,
                                       uint32_t& l01, uint32_t& l23) {
    __nv_bfloat16 h0 = __float2bfloat16_rn(v.x);
    __nv_bfloat16 h1 = __float2bfloat16_rn(v.y);
    __nv_bfloat16 h2 = __float2bfloat16_rn(v.z);
    __nv_bfloat16 h3 = __float2bfloat16_rn(v.w);
    __nv_bfloat16 q0 = __float2bfloat16_rn(v.x - __bfloat162float(h0));
    __nv_bfloat16 q1 = __float2bfloat16_rn(v.y - __bfloat162float(h1));
    __nv_bfloat16 q2 = __float2bfloat16_rn(v.z - __bfloat162float(h2));
    __nv_bfloat16 q3 = __float2bfloat16_rn(v.w - __bfloat162float(h3));
    h01 = (uint32_t)__bfloat16_as_ushort(h0) | ((uint32_t)__bfloat16_as_ushort(h1) << 16);
    h23 = (uint32_t)__bfloat16_as_ushort(h2) | ((uint32_t)__bfloat16_as_ushort(h3) << 16);
    l01 = (uint32_t)__bfloat16_as_ushort(q0) | ((uint32_t)__bfloat16_as_ushort(q1) << 16);
    l23 = (uint32_t)__bfloat16_as_ushort(q2) | ((uint32_t)__bfloat16_as_ushort(q3) << 16);
}
__device__ __forceinline__ void pack2(float a, float b, uint32_t& h, uint32_t& lo) {
    __nv_bfloat16 h0 = __float2bfloat16_rn(a), h1 = __float2bfloat16_rn(b);
    __nv_bfloat16 l0 = __float2bfloat16_rn(a - __bfloat162float(h0));
    __nv_bfloat16 l1 = __float2bfloat16_rn(b - __bfloat162float(h1));
    h  = (uint32_t)__bfloat16_as_ushort(h0) | ((uint32_t)__bfloat16_as_ushort(h1) << 16);
    lo = (uint32_t)__bfloat16_as_ushort(l0) | ((uint32_t)__bfloat16_as_ushort(l1) << 16);
}
__device__ __forceinline__ float2 pairval(uint32_t h, uint32_t l, float iv) {
    float2 fh = __bfloat1622float2(*(__nv_bfloat162*)&h);
    float2 fl = __bfloat1622float2(*(__nv_bfloat162*)&l);
    return make_float2((fh.x + fl.x) * iv, (fh.y + fl.y) * iv);
}

// ---------------- Kernel A: mask -> bitmask ----------------
__global__ __launch_bounds__(256) void mask_compress(const int* __restrict__ mask) {
    int w = blockIdx.x * 256 + threadIdx.x;
    const int4* m4 = (const int4*)mask + (size_t)w * 8;
    uint32_t b = 0;
    #pragma unroll
    for (int i = 0; i < 8; i++) {
        int4 v = m4[i];
        b |= (uint32_t)(v.x != 0) << (i * 4 + 0);
        b |= (uint32_t)(v.y != 0) << (i * 4 + 1);
        b |= (uint32_t)(v.z != 0) << (i * 4 + 2);
        b |= (uint32_t)(v.w != 0) << (i * 4 + 3);
    }
    g_mbits[w] = b;
}

// ---------------- Kernel B: fp32 -> bf16 hi/lo (Q and K in one launch) ------
__global__ __launch_bounds__(256) void split_prep2(const float* __restrict__ Q,
                                                   const float* __restrict__ K) {
    size_t i = (size_t)blockIdx.x * 256 + threadIdx.x;
    const float* X = blockIdx.y ? K : Q;
    float scale = blockIdx.y ? 1.0f : 0.125f;
    __nv_bfloat16* hi = blockIdx.y ? g_kh : g_qh;
    __nv_bfloat16* lo = blockIdx.y ? g_kl : g_ql;
    float4 v = ((const float4*)X)[i];
    v.x *= scale; v.y *= scale; v.z *= scale; v.w *= scale;
    uint32_t h01, h23, l01, l23;
    split4(v, h01, h23, l01, l23);
    ((uint2*)hi)[i] = make_uint2(h01, h23);
    ((uint2*)lo)[i] = make_uint2(l01, l23);
}

// ---------------- Kernel C: V -> Vt (bf16 hi/lo, [bh][n][k]) ----------------
__global__ __launch_bounds__(256) void vt_prep(const float* __restrict__ V) {
    __shared__ float tile[128][DIM + 1];
    const int bh = blockIdx.y;
    const int k0 = blockIdx.x * 128;
    const int tid = threadIdx.x;

    const float4* V4 = (const float4*)(V + ((size_t)bh * SEQ + k0) * DIM);
    #pragma unroll
    for (int p = 0; p < 8; p++) {
        int lin = tid + p * 256;
        int r = lin >> 4, j = lin & 15;
        float4 v = V4[lin];
        tile[r][j * 4 + 0] = v.x; tile[r][j * 4 + 1] = v.y;
        tile[r][j * 4 + 2] = v.z; tile[r][j * 4 + 3] = v.w;
    }
    __syncthreads();
    #pragma unroll
    for (int p = 0; p < 32; p++) {
        int lin = tid + p * 256;
        int n = lin >> 7, k = lin & 127;
        float x = tile[k][n];
        __nv_bfloat16 h = __float2bfloat16_rn(x);
        __nv_bfloat16 l = __float2bfloat16_rn(x - __bfloat162float(h));
        size_t o = ((size_t)bh * DIM + n) * SEQ + k0 + k;
        g_vt_hi[o] = h;
        g_vt_lo[o] = l;
    }
}

// ---------------- Kernel D: row-strip QK + exp + rowsums --------------------
// 128-col K chunks, SINGLE K buffer -> 73728 B smem -> 3 CTAs/SM.
// Cross-CTA overlap hides the exposed per-chunk K load.
__global__ __launch_bounds__(256, 3) void qk_exp_strip() {
    extern __shared__ char sm[];
    __shared__ float spsum[128];
    const uint32_t sb = smem_u32(sm);
    const int tid = threadIdx.x, wid = tid >> 5, l = tid & 31;
    const int m0 = blockIdx.x * 128, bh = blockIdx.y;

    if (tid < 128) spsum[tid] = 0.f;

    constexpr uint32_t QHI = 0, QLO = 18432, KHIs = 36864, KLOs = 55296;

    const uint4* Qh4 = (const uint4*)(g_qh + ((size_t)bh * SEQ + m0) * DIM);
    const uint4* Ql4 = (const uint4*)(g_ql + ((size_t)bh * SEQ + m0) * DIM);
    const uint4* Kh4 = (const uint4*)(g_kh + (size_t)bh * SEQ * DIM);
    const uint4* Kl4 = (const uint4*)(g_kl + (size_t)bh * SEQ * DIM);

    // K chunk loader: 128 rows x 8 uint4 per matrix
    auto issue_k = [&](int kt) {
        const uint4* kh = Kh4 + (size_t)kt * 1024;
        const uint4* kl = Kl4 + (size_t)kt * 1024;
        #pragma unroll
        for (int p = 0; p < 4; p++) {
            int lin = tid + p * 256;
            int r = lin >> 3, c = lin & 7;
            uint32_t off = (uint32_t)(r * RS + c * 8) * 2;
            cp16(sb + KHIs + off, kh + lin);
            cp16(sb + KLOs + off, kl + lin);
        }
    };

    // prologue: Q tiles
    #pragma unroll
    for (int p = 0; p < 4; p++) {
        int lin = tid + p * 256;
        int r = lin >> 3, c = lin & 7;
        uint32_t off = (uint32_t)(r * RS + c * 8) * 2;
        cp16(sb + QHI + off, Qh4 + lin);
        cp16(sb + QLO + off, Ql4 + lin);
    }
    issue_k(0);
    CP_COMMIT;
    CP_WAIT0;
    __syncthreads();

    const int wm = wid >> 2, wn = wid & 3;
    const int mbase = wm * 64, nbase = wn * 32;
    const int lr = l & 7, sub = l >> 3;
    const int arow_lane = lr + (sub & 1) * 8;
    const uint32_t akc = (uint32_t)((sub >> 1) * 8);
    const uint32_t bkc = (uint32_t)((sub & 1) * 8);
    const int g = l >> 2, q2 = (l & 3) * 2;

    float rs[4][2] = {};
    __nv_bfloat16* aho = g_ah + (size_t)bh * SEQ * SEQ;
    __nv_bfloat16* alo = g_al + (size_t)bh * SEQ * SEQ;

    for (int kt = 0; kt < 16; kt++) {
        float acc[4][4][4];
        #pragma unroll
        for (int a = 0; a < 4; a++)
            #pragma unroll
            for (int b = 0; b < 4; b++)
                #pragma unroll
                for (int c = 0; c < 4; c++) acc[a][b][c] = 0.f;

        #pragma unroll
        for (int ks = 0; ks < 4; ks++) {
            uint32_t ah[4][4], al[4][4];
            #pragma unroll
            for (int mt = 0; mt < 4; mt++) {
                int row = mbase + mt * 16 + arow_lane;
                uint32_t off = (uint32_t)(row * RS) * 2 + (akc + ks * 16) * 2;
                ldsm_x4(ah[mt], sb + QHI + off);
                ldsm_x4(al[mt], sb + QLO + off);
            }
            #pragma unroll
            for (int nt = 0; nt < 4; nt++) {
                int rowN = nbase + nt * 8 + lr;
                uint32_t off = (uint32_t)(rowN * RS) * 2 + (bkc + ks * 16) * 2;
                uint32_t bhf[2], blf[2];
                ldsm_x2(bhf, sb + KHIs + off);
                ldsm_x2(blf, sb + KLOs + off);
                #pragma unroll
                for (int mt = 0; mt < 4; mt++) {
                    mma16816(acc[mt][nt], ah[mt], bhf);
                    mma16816(acc[mt][nt], ah[mt], blf);
                    mma16816(acc[mt][nt], al[mt], bhf);
                }
            }
        }
        __syncthreads();     // MMA reads done; safe to overwrite K buffer
        if (kt + 1 < 16) {
            issue_k(kt + 1);
            CP_COMMIT;
        }

        // epilogue overlaps this CTA's own K load: mask + exp + p stores + row sums
        #pragma unroll
        for (int mt = 0; mt < 4; mt++) {
            int rl0 = mbase + mt * 16 + g;
            int row0 = m0 + rl0;
            uint32_t w0 = g_mbits[(size_t)row0 * 64 + kt * 4 + wn];
            uint32_t w1 = g_mbits[(size_t)(row0 + 8) * 64 + kt * 4 + wn];
            #pragma unroll
            for (int nt = 0; nt < 4; nt++) {
                int cb = nt * 8 + q2;
                float e0 = ((w0 >> cb) & 1)       ? __expf(acc[mt][nt][0]) : 0.f;
                float e1 = ((w0 >> (cb + 1)) & 1) ? __expf(acc[mt][nt][1]) : 0.f;
                float e2 = ((w1 >> cb) & 1)       ? __expf(acc[mt][nt][2]) : 0.f;
                float e3 = ((w1 >> (cb + 1)) & 1) ? __expf(acc[mt][nt][3]) : 0.f;
                rs[mt][0] += e0 + e1;
                rs[mt][1] += e2 + e3;
                size_t o0 = (size_t)row0 * SEQ + kt * 128 + nbase + cb;
                size_t o1 = o0 + (size_t)8 * SEQ;
                uint32_t h01, l01, h23, l23;
                pack2(e0, e1, h01, l01);
                pack2(e2, e3, h23, l23);
                *(uint32_t*)&aho[o0] = h01;
                *(uint32_t*)&alo[o0] = l01;
                *(uint32_t*)&aho[o1] = h23;
                *(uint32_t*)&alo[o1] = l23;
            }
        }

        if (kt + 1 < 16) {
            CP_WAIT0;
            __syncthreads();
        }
    }

    // strip row sums -> g_inv
    #pragma unroll
    for (int mt = 0; mt < 4; mt++) {
        float s0 = rs[mt][0], s1 = rs[mt][1];
        s0 += __shfl_xor_sync(0xffffffffu, s0, 1);
        s0 += __shfl_xor_sync(0xffffffffu, s0, 2);
        s1 += __shfl_xor_sync(0xffffffffu, s1, 1);
        s1 += __shfl_xor_sync(0xffffffffu, s1, 2);
        if ((l & 3) == 0) {
            atomicAdd(&spsum[mbase + mt * 16 + g], s0);
            atomicAdd(&spsum[mbase + mt * 16 + g + 8], s1);
        }
    }
    __syncthreads();
    if (tid < 128)
        g_inv[(size_t)bh * SEQ + m0 + tid] = 1.0f / spsum[tid];
}

// ---------------- Kernel E: out = p@V * inv, attn = p * inv -----------------
__global__ __launch_bounds__(256, 2) void attnv_fused(float* __restrict__ attn,
                                                      float* __restrict__ out) {
    extern __shared__ char sm[];
    __shared__ float sinv[128];
    const uint32_t sb = smem_u32(sm);
    const int tid = threadIdx.x, wid = tid >> 5, l = tid & 31;
    const int m0 = blockIdx.x * 128, bh = blockIdx.y;

    if (tid < 128) sinv[tid] = g_inv[(size_t)bh * SEQ + m0 + tid];

    constexpr uint32_t BSZ = 55296, AHI = 0, ALO = 18432, BHI = 36864, BLO = 46080;

    const uint4* Ah4 = (const uint4*)(g_ah + ((size_t)bh * SEQ + m0) * SEQ);
    const uint4* Al4 = (const uint4*)(g_al + ((size_t)bh * SEQ + m0) * SEQ);
    const uint4* Vh4 = (const uint4*)(g_vt_hi + (size_t)bh * DIM * SEQ);
    const uint4* Vl4 = (const uint4*)(g_vt_lo + (size_t)bh * DIM * SEQ);

    const int ar0 = tid >> 3, ac = tid & 7;

    auto issue_chunk = [&](int kt, uint32_t base) {
        #pragma unroll
        for (int p = 0; p < 4; p++) {
            int r = ar0 + p * 32;
            uint32_t off = (uint32_t)(r * RS + ac * 8) * 2;
            size_t gi = (size_t)r * 256 + kt * 8 + ac;
            cp16(sb + base + AHI + off, Ah4 + gi);
            cp16(sb + base + ALO + off, Al4 + gi);
        }
        #pragma unroll
        for (int p = 0; p < 2; p++) {
            int n = ar0 + p * 32;
            uint32_t off = (uint32_t)(n * RS + ac * 8) * 2;
            size_t gi = (size_t)n * 256 + kt * 8 + ac;
            cp16(sb + base + BHI + off, Vh4 + gi);
            cp16(sb + base + BLO + off, Vl4 + gi);
        }
    };

    issue_chunk(0, 0);
    CP_COMMIT;
    CP_WAIT0;
    __syncthreads();

    const int wm = wid >> 1, wn = wid & 1;
    const int mbase = wm * 32, nbase = wn * 32;
    const int lr = l & 7, sub = l >> 3;
    const int arow_lane = lr + (sub & 1) * 8;
    const uint32_t akc = (uint32_t)((sub >> 1) * 8);
    const uint32_t bkc = (uint32_t)((sub & 1) * 8);

    float acc[2][4][4];
    #pragma unroll
    for (int a = 0; a < 2; a++)
        #pragma unroll
        for (int b = 0; b < 4; b++)
            #pragma unroll
            for (int c = 0; c < 4; c++) acc[a][b][c] = 0.f;

    float* arow = attn + ((size_t)bh * SEQ + m0) * SEQ;

    for (int kt = 0; kt < 32; kt++) {
        if (kt + 1 < 32) {
            issue_chunk(kt + 1, (uint32_t)((kt + 1) & 1) * BSZ);
            CP_COMMIT;
        }
        const uint32_t base = (uint32_t)(kt & 1) * BSZ;

        // stream normalized fp32 attn from this chunk's smem copy
        #pragma unroll
        for (int p = 0; p < 4; p++) {
            int r = ar0 + p * 32;
            uint32_t off = (uint32_t)(r * RS + ac * 8) * 2;
            uint4 hh = *(const uint4*)(sm + base + AHI + off);
            uint4 ll = *(const uint4*)(sm + base + ALO + off);
            float iv = sinv[r];
            float2 a0 = pairval(hh.x, ll.x, iv);
            float2 a1 = pairval(hh.y, ll.y, iv);
            float2 a2 = pairval(hh.z, ll.z, iv);
            float2 a3 = pairval(hh.w, ll.w, iv);
            size_t o = (size_t)r * SEQ + kt * 64 + ac * 8;
            *(float4*)&arow[o]     = make_float4(a0.x, a0.y, a1.x, a1.y);
            *(float4*)&arow[o + 4] = make_float4(a2.x, a2.y, a3.x, a3.y);
        }

        #pragma unroll
        for (int ks = 0; ks < 4; ks++) {
            uint32_t ah[2][4], al[2][4];
            #pragma unroll
            for (int mt = 0; mt < 2; mt++) {
                int row = mbase + mt * 16 + arow_lane;
                uint32_t off = (uint32_t)(row * RS) * 2 + (akc + ks * 16) * 2;
                ldsm_x4(ah[mt], sb + base + AHI + off);
                ldsm_x4(al[mt], sb + base + ALO + off);
            }
            #pragma unroll
            for (int nt = 0; nt < 4; nt++) {
                int rowN = nbase + nt * 8 + lr;
                uint32_t off = (uint32_t)(rowN * RS) * 2 + (bkc + ks * 16) * 2;
                uint32_t bhf[2], blf[2];
                ldsm_x2(bhf, sb + base + BHI + off);
                ldsm_x2(blf, sb + base + BLO + off);
                #pragma unroll
                for (int mt = 0; mt < 2; mt++) {
                    mma16816(acc[mt][nt], ah[mt], bhf);
                    mma16816(acc[mt][nt], ah[mt], blf);
                    mma16816(acc[mt][nt], al[mt], bhf);
                }
            }
        }

        if (kt + 1 < 32) CP_WAIT0;
        __syncthreads();
    }

    const int g = l >> 2, q2 = (l & 3) * 2;
    float* ob = out + ((size_t)bh * SEQ + m0) * DIM;
    #pragma unroll
    for (int mt = 0; mt < 2; mt++) {
        int rl = mbase + mt * 16 + g;
        float iv0 = sinv[rl], iv1 = sinv[rl + 8];
        #pragma unroll
        for (int nt = 0; nt < 4; nt++) {
            int col = nbase + nt * 8 + q2;
            *(float2*)&ob[(size_t)rl * DIM + col] =
                make_float2(acc[mt][nt][0] * iv0, acc[mt][nt][1] * iv0);
            *(float2*)&ob[(size_t)(rl + 8) * DIM + col] =
                make_float2(acc[mt][nt][2] * iv1, acc[mt][nt][3] * iv1);
        }
    }
}

// ---------------- launch ----------------
extern "C" void kernel_launch(void* const* d_in, const int* in_sizes, int n_in,
                              void* d_out, int out_size) {
    const float* Q    = (const float*)d_in[0];
    const float* K    = (const float*)d_in[1];
    const float* V    = (const float*)d_in[2];
    const int*   mask = (const int*)d_in[3];

    float* out  = (float*)d_out;                      // [B,H,S,D]
    float* attn = out + (size_t)NBH * SEQ * DIM;      // [B,H,S,S]

    constexpr int QK_SMEM = 73728;
    constexpr int AV_SMEM = 110592;
    cudaFuncSetAttribute(qk_exp_strip, cudaFuncAttributeMaxDynamicSharedMemorySize, QK_SMEM);
    cudaFuncSetAttribute(attnv_fused, cudaFuncAttributeMaxDynamicSharedMemorySize, AV_SMEM);

    mask_compress<<<SEQ * (SEQ / 32) / 256, 256>>>(mask);

    dim3 gs((unsigned)((size_t)NBH * SEQ * DIM / 4 / 256), 2);
    split_prep2<<<gs, 256>>>(Q, K);

    dim3 g0(SEQ / 128, NBH);
    vt_prep<<<g0, 256>>>(V);

    dim3 g1(SEQ / 128, NBH);
    qk_exp_strip<<<g1, 256, QK_SMEM>>>();

    dim3 g2(SEQ / 128, NBH);
    attnv_fused<<<g2, 256, AV_SMEM>>>(attn, out);
}

// round 12
// speedup vs baseline: 1.3793x; 1.3793x over previous
#include <cuda_runtime.h>
#include <cuda_bf16.h>
#include <cstdint>

#define SEQ 2048
#define DIM 64
#define NBH 32   // B*H
#define RS 72    // smem row stride in bf16 (144B, conflict-free ldmatrix)

// Scratch (device globals; no allocs allowed)
__device__ __nv_bfloat16 g_qh[(size_t)NBH * SEQ * DIM];
__device__ __nv_bfloat16 g_ql[(size_t)NBH * SEQ * DIM];
__device__ __nv_bfloat16 g_kh[(size_t)NBH * SEQ * DIM];
__device__ __nv_bfloat16 g_kl[(size_t)NBH * SEQ * DIM];
__device__ __nv_bfloat16 g_vt_hi[(size_t)NBH * DIM * SEQ];
__device__ __nv_bfloat16 g_vt_lo[(size_t)NBH * DIM * SEQ];
__device__ __nv_bfloat16 g_ah[(size_t)NBH * SEQ * SEQ];   // unnormalized exp, hi
__device__ __nv_bfloat16 g_al[(size_t)NBH * SEQ * SEQ];   // unnormalized exp, lo
__device__ uint32_t g_mbits[(size_t)SEQ * (SEQ / 32)];

// ---------------- helpers ----------------
__device__ __forceinline__ uint32_t smem_u32(const void* p) {
    uint32_t a;
    asm("{ .reg .u64 t; cvta.to.shared.u64 t, %1; cvt.u32.u64 %0, t; }" : "=r"(a) : "l"(p));
    return a;
}
__device__ __forceinline__ void ldsm_x4(uint32_t r[4], uint32_t addr) {
    asm volatile("ldmatrix.sync.aligned.m8n8.x4.shared.b16 {%0,%1,%2,%3}, [%4];"
        : "=r"(r[0]), "=r"(r[1]), "=r"(r[2]), "=r"(r[3]) : "r"(addr));
}
__device__ __forceinline__ void ldsm_x2(uint32_t r[2], uint32_t addr) {
    asm volatile("ldmatrix.sync.aligned.m8n8.x2.shared.b16 {%0,%1}, [%2];"
        : "=r"(r[0]), "=r"(r[1]) : "r"(addr));
}
__device__ __forceinline__ void mma16816(float c[4], const uint32_t a[4], const uint32_t b[2]) {
    asm volatile(
        "mma.sync.aligned.m16n8k16.row.col.f32.bf16.bf16.f32 "
        "{%0,%1,%2,%3}, {%4,%5,%6,%7}, {%8,%9}, {%0,%1,%2,%3};"
        : "+f"(c[0]), "+f"(c[1]), "+f"(c[2]), "+f"(c[3])
        : "r"(a[0]), "r"(a[1]), "r"(a[2]), "r"(a[3]), "r"(b[0]), "r"(b[1]));
}
__device__ __forceinline__ void cp16(uint32_t dst, const void* src) {
    asm volatile("{ .reg .u64 g; cvta.to.global.u64 g, %1; cp.async.cg.shared.global [%0], [g], 16; }"
        :: "r"(dst), "l"(src) : "memory");
}
#define CP_COMMIT asm volatile("cp.async.commit_group;" ::: "memory")
#define CP_WAIT0  asm volatile("cp.async.wait_group 0;" ::: "memory")

__device__ __forceinline__ void split4(float4 v, uint32_t& h01, uint32_t& h23,
                                       uint32_t& l01, uint32_t& l23) {
    __nv_bfloat16 h0 = __float2bfloat16_rn(v.x);
    __nv_bfloat16 h1 = __float2bfloat16_rn(v.y);
    __nv_bfloat16 h2 = __float2bfloat16_rn(v.z);
    __nv_bfloat16 h3 = __float2bfloat16_rn(v.w);
    __nv_bfloat16 q0 = __float2bfloat16_rn(v.x - __bfloat162float(h0));
    __nv_bfloat16 q1 = __float2bfloat16_rn(v.y - __bfloat162float(h1));
    __nv_bfloat16 q2 = __float2bfloat16_rn(v.z - __bfloat162float(h2));
    __nv_bfloat16 q3 = __float2bfloat16_rn(v.w - __bfloat162float(h3));
    h01 = (uint32_t)__bfloat16_as_ushort(h0) | ((uint32_t)__bfloat16_as_ushort(h1) << 16);
    h23 = (uint32_t)__bfloat16_as_ushort(h2) | ((uint32_t)__bfloat16_as_ushort(h3) << 16);
    l01 = (uint32_t)__bfloat16_as_ushort(q0) | ((uint32_t)__bfloat16_as_ushort(q1) << 16);
    l23 = (uint32_t)__bfloat16_as_ushort(q2) | ((uint32_t)__bfloat16_as_ushort(q3) << 16);
}
__device__ __forceinline__ void pack2(float a, float b, uint32_t& h, uint32_t& lo) {
    __nv_bfloat16 h0 = __float2bfloat16_rn(a), h1 = __float2bfloat16_rn(b);
    __nv_bfloat16 l0 = __float2bfloat16_rn(a - __bfloat162float(h0));
    __nv_bfloat16 l1 = __float2bfloat16_rn(b - __bfloat162float(h1));
    h  = (uint32_t)__bfloat16_as_ushort(h0) | ((uint32_t)__bfloat16_as_ushort(h1) << 16);
    lo = (uint32_t)__bfloat16_as_ushort(l0) | ((uint32_t)__bfloat16_as_ushort(l1) << 16);
}
__device__ __forceinline__ float2 pairval(uint32_t h, uint32_t l, float iv) {
    float2 fh = __bfloat1622float2(*(__nv_bfloat162*)&h);
    float2 fl = __bfloat1622float2(*(__nv_bfloat162*)&l);
    return make_float2((fh.x + fl.x) * iv, (fh.y + fl.y) * iv);
}

// ---------------- Kernel A: mask -> bitmask ----------------
__global__ __launch_bounds__(256) void mask_compress(const int* __restrict__ mask) {
    int w = blockIdx.x * 256 + threadIdx.x;
    const int4* m4 = (const int4*)mask + (size_t)w * 8;
    uint32_t b = 0;
    #pragma unroll
    for (int i = 0; i < 8; i++) {
        int4 v = m4[i];
        b |= (uint32_t)(v.x != 0) << (i * 4 + 0);
        b |= (uint32_t)(v.y != 0) << (i * 4 + 1);
        b |= (uint32_t)(v.z != 0) << (i * 4 + 2);
        b |= (uint32_t)(v.w != 0) << (i * 4 + 3);
    }
    g_mbits[w] = b;
}

// ---------------- Kernel B: fp32 -> bf16 hi/lo (Q and K in one launch) ------
__global__ __launch_bounds__(256) void split_prep2(const float* __restrict__ Q,
                                                   const float* __restrict__ K) {
    size_t i = (size_t)blockIdx.x * 256 + threadIdx.x;
    const float* X = blockIdx.y ? K : Q;
    float scale = blockIdx.y ? 1.0f : 0.125f;
    __nv_bfloat16* hi = blockIdx.y ? g_kh : g_qh;
    __nv_bfloat16* lo = blockIdx.y ? g_kl : g_ql;
    float4 v = ((const float4*)X)[i];
    v.x *= scale; v.y *= scale; v.z *= scale; v.w *= scale;
    uint32_t h01, h23, l01, l23;
    split4(v, h01, h23, l01, l23);
    ((uint2*)hi)[i] = make_uint2(h01, h23);
    ((uint2*)lo)[i] = make_uint2(l01, l23);
}

// ---------------- Kernel C: V -> Vt (bf16 hi/lo, [bh][n][k]) ----------------
__global__ __launch_bounds__(256) void vt_prep(const float* __restrict__ V) {
    __shared__ float tile[128][DIM + 1];
    const int bh = blockIdx.y;
    const int k0 = blockIdx.x * 128;
    const int tid = threadIdx.x;

    const float4* V4 = (const float4*)(V + ((size_t)bh * SEQ + k0) * DIM);
    #pragma unroll
    for (int p = 0; p < 8; p++) {
        int lin = tid + p * 256;
        int r = lin >> 4, j = lin & 15;
        float4 v = V4[lin];
        tile[r][j * 4 + 0] = v.x; tile[r][j * 4 + 1] = v.y;
        tile[r][j * 4 + 2] = v.z; tile[r][j * 4 + 3] = v.w;
    }
    __syncthreads();
    #pragma unroll
    for (int p = 0; p < 32; p++) {
        int lin = tid + p * 256;
        int n = lin >> 7, k = lin & 127;
        float x = tile[k][n];
        __nv_bfloat16 h = __float2bfloat16_rn(x);
        __nv_bfloat16 l = __float2bfloat16_rn(x - __bfloat162float(h));
        size_t o = ((size_t)bh * DIM + n) * SEQ + k0 + k;
        g_vt_hi[o] = h;
        g_vt_lo[o] = l;
    }
}

// ---------------- Fused strip kernel: QK+exp+rowsum then p@V + attn ---------
// Phase 1 smem: Q hi [0,18432) Q lo [18432,36864), K dbuf [36864, 110592)
// Phase 2 smem: A hi [0,18432) A lo [18432,36864), V hi [36864,46080) V lo [46080,55296), dbuf x2
__global__ __launch_bounds__(256, 2) void fused_strip(float* __restrict__ attn,
                                                      float* __restrict__ out) {
    extern __shared__ char sm[];
    __shared__ float spsum[128];
    __shared__ float sinv[128];
    const uint32_t sb = smem_u32(sm);
    const int tid = threadIdx.x, wid = tid >> 5, l = tid & 31;
    const int m0 = blockIdx.x * 128, bh = blockIdx.y;

    if (tid < 128) spsum[tid] = 0.f;

    const int lr = l & 7, sub = l >> 3;
    const int arow_lane = lr + (sub & 1) * 8;
    const uint32_t akc = (uint32_t)((sub >> 1) * 8);
    const uint32_t bkc = (uint32_t)((sub & 1) * 8);
    const int g = l >> 2, q2 = (l & 3) * 2;

    __nv_bfloat16* aho = g_ah + (size_t)bh * SEQ * SEQ;
    __nv_bfloat16* alo = g_al + (size_t)bh * SEQ * SEQ;

    // ================= PHASE 1: QK + exp + p store + row sums =================
    {
        constexpr uint32_t QHI = 0, QLO = 18432, KB = 36864, KBSZ = 36864;

        const uint4* Qh4 = (const uint4*)(g_qh + ((size_t)bh * SEQ + m0) * DIM);
        const uint4* Ql4 = (const uint4*)(g_ql + ((size_t)bh * SEQ + m0) * DIM);
        const uint4* Kh4 = (const uint4*)(g_kh + (size_t)bh * SEQ * DIM);
        const uint4* Kl4 = (const uint4*)(g_kl + (size_t)bh * SEQ * DIM);

        auto issue_k = [&](int kt, uint32_t dbase) {
            const uint4* kh = Kh4 + (size_t)kt * 1024;
            const uint4* kl = Kl4 + (size_t)kt * 1024;
            #pragma unroll
            for (int p = 0; p < 4; p++) {
                int lin = tid + p * 256;
                int r = lin >> 3, c = lin & 7;
                uint32_t off = (uint32_t)(r * RS + c * 8) * 2;
                cp16(dbase + off, kh + lin);
                cp16(dbase + 18432 + off, kl + lin);
            }
        };

        #pragma unroll
        for (int p = 0; p < 4; p++) {
            int lin = tid + p * 256;
            int r = lin >> 3, c = lin & 7;
            uint32_t off = (uint32_t)(r * RS + c * 8) * 2;
            cp16(sb + QHI + off, Qh4 + lin);
            cp16(sb + QLO + off, Ql4 + lin);
        }
        CP_COMMIT;
        issue_k(0, sb + KB);
        CP_COMMIT;
        CP_WAIT0;
        __syncthreads();

        const int wm = wid >> 2, wn = wid & 3;
        const int mbase = wm * 64, nbase = wn * 32;

        float rs[4][2] = {};

        for (int kt = 0; kt < 16; kt++) {
            if (kt + 1 < 16) {
                issue_k(kt + 1, sb + KB + (uint32_t)((kt + 1) & 1) * KBSZ);
                CP_COMMIT;
            }
            const uint32_t KHIb = sb + KB + (uint32_t)(kt & 1) * KBSZ;
            const uint32_t KLOb = KHIb + 18432;

            float acc[4][4][4];
            #pragma unroll
            for (int a = 0; a < 4; a++)
                #pragma unroll
                for (int b = 0; b < 4; b++)
                    #pragma unroll
                    for (int c = 0; c < 4; c++) acc[a][b][c] = 0.f;

            #pragma unroll
            for (int ks = 0; ks < 4; ks++) {
                uint32_t ah[4][4], al[4][4];
                #pragma unroll
                for (int mt = 0; mt < 4; mt++) {
                    int row = mbase + mt * 16 + arow_lane;
                    uint32_t off = (uint32_t)(row * RS) * 2 + (akc + ks * 16) * 2;
                    ldsm_x4(ah[mt], sb + QHI + off);
                    ldsm_x4(al[mt], sb + QLO + off);
                }
                #pragma unroll
                for (int nt = 0; nt < 4; nt++) {
                    int rowN = nbase + nt * 8 + lr;
                    uint32_t off = (uint32_t)(rowN * RS) * 2 + (bkc + ks * 16) * 2;
                    uint32_t bhf[2], blf[2];
                    ldsm_x2(bhf, KHIb + off);
                    ldsm_x2(blf, KLOb + off);
                    #pragma unroll
                    for (int mt = 0; mt < 4; mt++) {
                        mma16816(acc[mt][nt], ah[mt], bhf);
                        mma16816(acc[mt][nt], ah[mt], blf);
                        mma16816(acc[mt][nt], al[mt], bhf);
                    }
                }
            }

            #pragma unroll
            for (int mt = 0; mt < 4; mt++) {
                int rl0 = mbase + mt * 16 + g;
                int row0 = m0 + rl0;
                uint32_t w0 = g_mbits[(size_t)row0 * 64 + kt * 4 + wn];
                uint32_t w1 = g_mbits[(size_t)(row0 + 8) * 64 + kt * 4 + wn];
                #pragma unroll
                for (int nt = 0; nt < 4; nt++) {
                    int cb = nt * 8 + q2;
                    float e0 = ((w0 >> cb) & 1)       ? __expf(acc[mt][nt][0]) : 0.f;
                    float e1 = ((w0 >> (cb + 1)) & 1) ? __expf(acc[mt][nt][1]) : 0.f;
                    float e2 = ((w1 >> cb) & 1)       ? __expf(acc[mt][nt][2]) : 0.f;
                    float e3 = ((w1 >> (cb + 1)) & 1) ? __expf(acc[mt][nt][3]) : 0.f;
                    rs[mt][0] += e0 + e1;
                    rs[mt][1] += e2 + e3;
                    size_t o0 = (size_t)row0 * SEQ + kt * 128 + nbase + cb;
                    size_t o1 = o0 + (size_t)8 * SEQ;
                    uint32_t h01, l01, h23, l23;
                    pack2(e0, e1, h01, l01);
                    pack2(e2, e3, h23, l23);
                    *(uint32_t*)&aho[o0] = h01;
                    *(uint32_t*)&alo[o0] = l01;
                    *(uint32_t*)&aho[o1] = h23;
                    *(uint32_t*)&alo[o1] = l23;
                }
            }

            if (kt + 1 < 16) CP_WAIT0;
            __syncthreads();
        }

        // row sums -> sinv (in smem; no global round trip)
        #pragma unroll
        for (int mt = 0; mt < 4; mt++) {
            float s0 = rs[mt][0], s1 = rs[mt][1];
            s0 += __shfl_xor_sync(0xffffffffu, s0, 1);
            s0 += __shfl_xor_sync(0xffffffffu, s0, 2);
            s1 += __shfl_xor_sync(0xffffffffu, s1, 1);
            s1 += __shfl_xor_sync(0xffffffffu, s1, 2);
            if ((l & 3) == 0) {
                atomicAdd(&spsum[mbase + mt * 16 + g], s0);
                atomicAdd(&spsum[mbase + mt * 16 + g + 8], s1);
            }
        }
        __syncthreads();
        if (tid < 128) sinv[tid] = 1.0f / spsum[tid];
        __syncthreads();
    }

    // ================= PHASE 2: out = p@V * inv, attn = p * inv ===============
    {
        constexpr uint32_t BSZ = 55296, AHI = 0, ALO = 18432, BHI = 36864, BLO = 46080;

        const uint4* Ah4 = (const uint4*)(aho + (size_t)m0 * SEQ);
        const uint4* Al4 = (const uint4*)(alo + (size_t)m0 * SEQ);
        const uint4* Vh4 = (const uint4*)(g_vt_hi + (size_t)bh * DIM * SEQ);
        const uint4* Vl4 = (const uint4*)(g_vt_lo + (size_t)bh * DIM * SEQ);

        const int ar0 = tid >> 3, ac = tid & 7;

        auto issue_chunk = [&](int kt, uint32_t base) {
            #pragma unroll
            for (int p = 0; p < 4; p++) {
                int r = ar0 + p * 32;
                uint32_t off = (uint32_t)(r * RS + ac * 8) * 2;
                size_t gi = (size_t)r * 256 + kt * 8 + ac;
                cp16(sb + base + AHI + off, Ah4 + gi);
                cp16(sb + base + ALO + off, Al4 + gi);
            }
            #pragma unroll
            for (int p = 0; p < 2; p++) {
                int n = ar0 + p * 32;
                uint32_t off = (uint32_t)(n * RS + ac * 8) * 2;
                size_t gi = (size_t)n * 256 + kt * 8 + ac;
                cp16(sb + base + BHI + off, Vh4 + gi);
                cp16(sb + base + BLO + off, Vl4 + gi);
            }
        };

        issue_chunk(0, 0);
        CP_COMMIT;
        CP_WAIT0;
        __syncthreads();

        const int wm = wid >> 1, wn = wid & 1;
        const int mbase = wm * 32, nbase = wn * 32;

        float acc[2][4][4];
        #pragma unroll
        for (int a = 0; a < 2; a++)
            #pragma unroll
            for (int b = 0; b < 4; b++)
                #pragma unroll
                for (int c = 0; c < 4; c++) acc[a][b][c] = 0.f;

        float* arow = attn + ((size_t)bh * SEQ + m0) * SEQ;

        for (int kt = 0; kt < 32; kt++) {
            if (kt + 1 < 32) {
                issue_chunk(kt + 1, (uint32_t)((kt + 1) & 1) * BSZ);
                CP_COMMIT;
            }
            const uint32_t base = (uint32_t)(kt & 1) * BSZ;

            // stream normalized fp32 attn from this chunk's smem copy
            #pragma unroll
            for (int p = 0; p < 4; p++) {
                int r = ar0 + p * 32;
                uint32_t off = (uint32_t)(r * RS + ac * 8) * 2;
                uint4 hh = *(const uint4*)(sm + base + AHI + off);
                uint4 ll = *(const uint4*)(sm + base + ALO + off);
                float iv = sinv[r];
                float2 a0 = pairval(hh.x, ll.x, iv);
                float2 a1 = pairval(hh.y, ll.y, iv);
                float2 a2 = pairval(hh.z, ll.z, iv);
                float2 a3 = pairval(hh.w, ll.w, iv);
                size_t o = (size_t)r * SEQ + kt * 64 + ac * 8;
                *(float4*)&arow[o]     = make_float4(a0.x, a0.y, a1.x, a1.y);
                *(float4*)&arow[o + 4] = make_float4(a2.x, a2.y, a3.x, a3.y);
            }

            #pragma unroll
            for (int ks = 0; ks < 4; ks++) {
                uint32_t ah[2][4], al[2][4];
                #pragma unroll
                for (int mt = 0; mt < 2; mt++) {
                    int row = mbase + mt * 16 + arow_lane;
                    uint32_t off = (uint32_t)(row * RS) * 2 + (akc + ks * 16) * 2;
                    ldsm_x4(ah[mt], sb + base + AHI + off);
                    ldsm_x4(al[mt], sb + base + ALO + off);
                }
                #pragma unroll
                for (int nt = 0; nt < 4; nt++) {
                    int rowN = nbase + nt * 8 + lr;
                    uint32_t off = (uint32_t)(rowN * RS) * 2 + (bkc + ks * 16) * 2;
                    uint32_t bhf[2], blf[2];
                    ldsm_x2(bhf, sb + base + BHI + off);
                    ldsm_x2(blf, sb + base + BLO + off);
                    #pragma unroll
                    for (int mt = 0; mt < 2; mt++) {
                        mma16816(acc[mt][nt], ah[mt], bhf);
                        mma16816(acc[mt][nt], ah[mt], blf);
                        mma16816(acc[mt][nt], al[mt], bhf);
                    }
                }
            }

            if (kt + 1 < 32) CP_WAIT0;
            __syncthreads();
        }

        float* ob = out + ((size_t)bh * SEQ + m0) * DIM;
        #pragma unroll
        for (int mt = 0; mt < 2; mt++) {
            int rl = mbase + mt * 16 + g;
            float iv0 = sinv[rl], iv1 = sinv[rl + 8];
            #pragma unroll
            for (int nt = 0; nt < 4; nt++) {
                int col = nbase + nt * 8 + q2;
                *(float2*)&ob[(size_t)rl * DIM + col] =
                    make_float2(acc[mt][nt][0] * iv0, acc[mt][nt][1] * iv0);
                *(float2*)&ob[(size_t)(rl + 8) * DIM + col] =
                    make_float2(acc[mt][nt][2] * iv1, acc[mt][nt][3] * iv1);
            }
        }
    }
}

// ---------------- launch ----------------
extern "C" void kernel_launch(void* const* d_in, const int* in_sizes, int n_in,
                              void* d_out, int out_size) {
    const float* Q    = (const float*)d_in[0];
    const float* K    = (const float*)d_in[1];
    const float* V    = (const float*)d_in[2];
    const int*   mask = (const int*)d_in[3];

    float* out  = (float*)d_out;                      // [B,H,S,D]
    float* attn = out + (size_t)NBH * SEQ * DIM;      // [B,H,S,S]

    constexpr int STRIP_SMEM = 110592;
    cudaFuncSetAttribute(fused_strip, cudaFuncAttributeMaxDynamicSharedMemorySize, STRIP_SMEM);

    mask_compress<<<SEQ * (SEQ / 32) / 256, 256>>>(mask);

    dim3 gs((unsigned)((size_t)NBH * SEQ * DIM / 4 / 256), 2);
    split_prep2<<<gs, 256>>>(Q, K);

    dim3 g0(SEQ / 128, NBH);
    vt_prep<<<g0, 256>>>(V);

    dim3 g1(SEQ / 128, NBH);
    fused_strip<<<g1, 256, STRIP_SMEM>>>(attn, out);
}

// round 13
// speedup vs baseline: 1.7404x; 1.2618x over previous
#include <cuda_runtime.h>
#include <cuda_bf16.h>
#include <cuda_fp16.h>
#include <cstdint>

#define SEQ 2048
#define DIM 64
#define NBH 32   // B*H
#define RS 72    // smem row stride in 16-bit elems (144B, conflict-free ldmatrix)

// Scratch (device globals; no allocs allowed)
__device__ __nv_bfloat16 g_qh[(size_t)NBH * SEQ * DIM];
__device__ __nv_bfloat16 g_ql[(size_t)NBH * SEQ * DIM];
__device__ __nv_bfloat16 g_kh[(size_t)NBH * SEQ * DIM];
__device__ __nv_bfloat16 g_kl[(size_t)NBH * SEQ * DIM];
__device__ __half g_vt_hi[(size_t)NBH * DIM * SEQ];
__device__ __half g_vt_lo[(size_t)NBH * DIM * SEQ];
__device__ __half g_p[(size_t)NBH * SEQ * SEQ];       // unnormalized exp(s), fp16
__device__ uint32_t g_mbits[(size_t)SEQ * (SEQ / 32)];

// ---------------- helpers ----------------
__device__ __forceinline__ uint32_t smem_u32(const void* p) {
    uint32_t a;
    asm("{ .reg .u64 t; cvta.to.shared.u64 t, %1; cvt.u32.u64 %0, t; }" : "=r"(a) : "l"(p));
    return a;
}
__device__ __forceinline__ void ldsm_x4(uint32_t r[4], uint32_t addr) {
    asm volatile("ldmatrix.sync.aligned.m8n8.x4.shared.b16 {%0,%1,%2,%3}, [%4];"
        : "=r"(r[0]), "=r"(r[1]), "=r"(r[2]), "=r"(r[3]) : "r"(addr));
}
__device__ __forceinline__ void ldsm_x2(uint32_t r[2], uint32_t addr) {
    asm volatile("ldmatrix.sync.aligned.m8n8.x2.shared.b16 {%0,%1}, [%2];"
        : "=r"(r[0]), "=r"(r[1]) : "r"(addr));
}
__device__ __forceinline__ void mma16816(float c[4], const uint32_t a[4], const uint32_t b[2]) {
    asm volatile(
        "mma.sync.aligned.m16n8k16.row.col.f32.bf16.bf16.f32 "
        "{%0,%1,%2,%3}, {%4,%5,%6,%7}, {%8,%9}, {%0,%1,%2,%3};"
        : "+f"(c[0]), "+f"(c[1]), "+f"(c[2]), "+f"(c[3])
        : "r"(a[0]), "r"(a[1]), "r"(a[2]), "r"(a[3]), "r"(b[0]), "r"(b[1]));
}
__device__ __forceinline__ void mma16816h(float c[4], const uint32_t a[4], const uint32_t b[2]) {
    asm volatile(
        "mma.sync.aligned.m16n8k16.row.col.f32.f16.f16.f32 "
        "{%0,%1,%2,%3}, {%4,%5,%6,%7}, {%8,%9}, {%0,%1,%2,%3};"
        : "+f"(c[0]), "+f"(c[1]), "+f"(c[2]), "+f"(c[3])
        : "r"(a[0]), "r"(a[1]), "r"(a[2]), "r"(a[3]), "r"(b[0]), "r"(b[1]));
}
__device__ __forceinline__ void cp16(uint32_t dst, const void* src) {
    asm volatile("{ .reg .u64 g; cvta.to.global.u64 g, %1; cp.async.cg.shared.global [%0], [g], 16; }"
        :: "r"(dst), "l"(src) : "memory");
}
#define CP_COMMIT asm volatile("cp.async.commit_group;" ::: "memory")
#define CP_WAIT0  asm volatile("cp.async.wait_group 0;" ::: "memory")

__device__ __forceinline__ void split4(float4 v, uint32_t& h01, uint32_t& h23,
                                       uint32_t& l01, uint32_t& l23) {
    __nv_bfloat16 h0 = __float2bfloat16_rn(v.x);
    __nv_bfloat16 h1 = __float2bfloat16_rn(v.y);
    __nv_bfloat16 h2 = __float2bfloat16_rn(v.z);
    __nv_bfloat16 h3 = __float2bfloat16_rn(v.w);
    __nv_bfloat16 q0 = __float2bfloat16_rn(v.x - __bfloat162float(h0));
    __nv_bfloat16 q1 = __float2bfloat16_rn(v.y - __bfloat162float(h1));
    __nv_bfloat16 q2 = __float2bfloat16_rn(v.z - __bfloat162float(h2));
    __nv_bfloat16 q3 = __float2bfloat16_rn(v.w - __bfloat162float(h3));
    h01 = (uint32_t)__bfloat16_as_ushort(h0) | ((uint32_t)__bfloat16_as_ushort(h1) << 16);
    h23 = (uint32_t)__bfloat16_as_ushort(h2) | ((uint32_t)__bfloat16_as_ushort(h3) << 16);
    l01 = (uint32_t)__bfloat16_as_ushort(q0) | ((uint32_t)__bfloat16_as_ushort(q1) << 16);
    l23 = (uint32_t)__bfloat16_as_ushort(q2) | ((uint32_t)__bfloat16_as_ushort(q3) << 16);
}

// ---------------- Kernel A: mask -> bitmask ----------------
__global__ __launch_bounds__(256) void mask_compress(const int* __restrict__ mask) {
    int w = blockIdx.x * 256 + threadIdx.x;
    const int4* m4 = (const int4*)mask + (size_t)w * 8;
    uint32_t b = 0;
    #pragma unroll
    for (int i = 0; i < 8; i++) {
        int4 v = m4[i];
        b |= (uint32_t)(v.x != 0) << (i * 4 + 0);
        b |= (uint32_t)(v.y != 0) << (i * 4 + 1);
        b |= (uint32_t)(v.z != 0) << (i * 4 + 2);
        b |= (uint32_t)(v.w != 0) << (i * 4 + 3);
    }
    g_mbits[w] = b;
}

// ---------------- Kernel B: fp32 -> bf16 hi/lo (Q and K in one launch) ------
__global__ __launch_bounds__(256) void split_prep2(const float* __restrict__ Q,
                                                   const float* __restrict__ K) {
    size_t i = (size_t)blockIdx.x * 256 + threadIdx.x;
    const float* X = blockIdx.y ? K : Q;
    float scale = blockIdx.y ? 1.0f : 0.125f;
    __nv_bfloat16* hi = blockIdx.y ? g_kh : g_qh;
    __nv_bfloat16* lo = blockIdx.y ? g_kl : g_ql;
    float4 v = ((const float4*)X)[i];
    v.x *= scale; v.y *= scale; v.z *= scale; v.w *= scale;
    uint32_t h01, h23, l01, l23;
    split4(v, h01, h23, l01, l23);
    ((uint2*)hi)[i] = make_uint2(h01, h23);
    ((uint2*)lo)[i] = make_uint2(l01, l23);
}

// ---------------- Kernel C: V -> Vt (fp16 hi/lo, [bh][n][k]) ----------------
__global__ __launch_bounds__(256) void vt_prep(const float* __restrict__ V) {
    __shared__ float tile[128][DIM + 1];
    const int bh = blockIdx.y;
    const int k0 = blockIdx.x * 128;
    const int tid = threadIdx.x;

    const float4* V4 = (const float4*)(V + ((size_t)bh * SEQ + k0) * DIM);
    #pragma unroll
    for (int p = 0; p < 8; p++) {
        int lin = tid + p * 256;
        int r = lin >> 4, j = lin & 15;
        float4 v = V4[lin];
        tile[r][j * 4 + 0] = v.x; tile[r][j * 4 + 1] = v.y;
        tile[r][j * 4 + 2] = v.z; tile[r][j * 4 + 3] = v.w;
    }
    __syncthreads();
    #pragma unroll
    for (int p = 0; p < 32; p++) {
        int lin = tid + p * 256;
        int n = lin >> 7, k = lin & 127;
        float x = tile[k][n];
        __half h = __float2half_rn(x);
        __half l = __float2half_rn(x - __half2float(h));
        size_t o = ((size_t)bh * DIM + n) * SEQ + k0 + k;
        g_vt_hi[o] = h;
        g_vt_lo[o] = l;
    }
}

// ---------------- Fused strip kernel -----------------------------------------
// Phase 1 smem: Q hi [0,18432) Q lo [18432,36864), K dbuf [36864,110592)
// Phase 2 smem: per buf { A fp16 [0,18432), V hi [18432,27648), V lo [27648,36864) } x2
__global__ __launch_bounds__(256, 2) void fused_strip(float* __restrict__ attn,
                                                      float* __restrict__ out) {
    extern __shared__ char sm[];
    __shared__ float spsum[128];
    __shared__ float sinv[128];
    const uint32_t sb = smem_u32(sm);
    const int tid = threadIdx.x, wid = tid >> 5, l = tid & 31;
    const int m0 = blockIdx.x * 128, bh = blockIdx.y;

    if (tid < 128) spsum[tid] = 0.f;

    const int lr = l & 7, sub = l >> 3;
    const int arow_lane = lr + (sub & 1) * 8;
    const uint32_t akc = (uint32_t)((sub >> 1) * 8);
    const uint32_t bkc = (uint32_t)((sub & 1) * 8);
    const int g = l >> 2, q2 = (l & 3) * 2;

    __half* pbase = g_p + (size_t)bh * SEQ * SEQ;

    // ================= PHASE 1: QK + exp + p store (fp16) + row sums ==========
    {
        constexpr uint32_t QHI = 0, QLO = 18432, KB = 36864, KBSZ = 36864;

        const uint4* Qh4 = (const uint4*)(g_qh + ((size_t)bh * SEQ + m0) * DIM);
        const uint4* Ql4 = (const uint4*)(g_ql + ((size_t)bh * SEQ + m0) * DIM);
        const uint4* Kh4 = (const uint4*)(g_kh + (size_t)bh * SEQ * DIM);
        const uint4* Kl4 = (const uint4*)(g_kl + (size_t)bh * SEQ * DIM);

        auto issue_k = [&](int kt, uint32_t dbase) {
            const uint4* kh = Kh4 + (size_t)kt * 1024;
            const uint4* kl = Kl4 + (size_t)kt * 1024;
            #pragma unroll
            for (int p = 0; p < 4; p++) {
                int lin = tid + p * 256;
                int r = lin >> 3, c = lin & 7;
                uint32_t off = (uint32_t)(r * RS + c * 8) * 2;
                cp16(dbase + off, kh + lin);
                cp16(dbase + 18432 + off, kl + lin);
            }
        };

        #pragma unroll
        for (int p = 0; p < 4; p++) {
            int lin = tid + p * 256;
            int r = lin >> 3, c = lin & 7;
            uint32_t off = (uint32_t)(r * RS + c * 8) * 2;
            cp16(sb + QHI + off, Qh4 + lin);
            cp16(sb + QLO + off, Ql4 + lin);
        }
        CP_COMMIT;
        issue_k(0, sb + KB);
        CP_COMMIT;
        CP_WAIT0;
        __syncthreads();

        const int wm = wid >> 2, wn = wid & 3;
        const int mbase = wm * 64, nbase = wn * 32;

        float rs[4][2] = {};

        for (int kt = 0; kt < 16; kt++) {
            if (kt + 1 < 16) {
                issue_k(kt + 1, sb + KB + (uint32_t)((kt + 1) & 1) * KBSZ);
                CP_COMMIT;
            }
            const uint32_t KHIb = sb + KB + (uint32_t)(kt & 1) * KBSZ;
            const uint32_t KLOb = KHIb + 18432;

            float acc[4][4][4];
            #pragma unroll
            for (int a = 0; a < 4; a++)
                #pragma unroll
                for (int b = 0; b < 4; b++)
                    #pragma unroll
                    for (int c = 0; c < 4; c++) acc[a][b][c] = 0.f;

            #pragma unroll
            for (int ks = 0; ks < 4; ks++) {
                uint32_t ah[4][4], al[4][4];
                #pragma unroll
                for (int mt = 0; mt < 4; mt++) {
                    int row = mbase + mt * 16 + arow_lane;
                    uint32_t off = (uint32_t)(row * RS) * 2 + (akc + ks * 16) * 2;
                    ldsm_x4(ah[mt], sb + QHI + off);
                    ldsm_x4(al[mt], sb + QLO + off);
                }
                #pragma unroll
                for (int nt = 0; nt < 4; nt++) {
                    int rowN = nbase + nt * 8 + lr;
                    uint32_t off = (uint32_t)(rowN * RS) * 2 + (bkc + ks * 16) * 2;
                    uint32_t bhf[2], blf[2];
                    ldsm_x2(bhf, KHIb + off);
                    ldsm_x2(blf, KLOb + off);
                    #pragma unroll
                    for (int mt = 0; mt < 4; mt++) {
                        mma16816(acc[mt][nt], ah[mt], bhf);
                        mma16816(acc[mt][nt], ah[mt], blf);
                        mma16816(acc[mt][nt], al[mt], bhf);
                    }
                }
            }

            #pragma unroll
            for (int mt = 0; mt < 4; mt++) {
                int rl0 = mbase + mt * 16 + g;
                int row0 = m0 + rl0;
                uint32_t w0 = g_mbits[(size_t)row0 * 64 + kt * 4 + wn];
                uint32_t w1 = g_mbits[(size_t)(row0 + 8) * 64 + kt * 4 + wn];
                #pragma unroll
                for (int nt = 0; nt < 4; nt++) {
                    int cb = nt * 8 + q2;
                    float e0 = ((w0 >> cb) & 1)       ? __expf(acc[mt][nt][0]) : 0.f;
                    float e1 = ((w0 >> (cb + 1)) & 1) ? __expf(acc[mt][nt][1]) : 0.f;
                    float e2 = ((w1 >> cb) & 1)       ? __expf(acc[mt][nt][2]) : 0.f;
                    float e3 = ((w1 >> (cb + 1)) & 1) ? __expf(acc[mt][nt][3]) : 0.f;
                    rs[mt][0] += e0 + e1;
                    rs[mt][1] += e2 + e3;
                    size_t o0 = (size_t)row0 * SEQ + kt * 128 + nbase + cb;
                    size_t o1 = o0 + (size_t)8 * SEQ;
                    __half2 p01 = __floats2half2_rn(e0, e1);
                    __half2 p23 = __floats2half2_rn(e2, e3);
                    *(__half2*)&pbase[o0] = p01;
                    *(__half2*)&pbase[o1] = p23;
                }
            }

            if (kt + 1 < 16) CP_WAIT0;
            __syncthreads();
        }

        #pragma unroll
        for (int mt = 0; mt < 4; mt++) {
            float s0 = rs[mt][0], s1 = rs[mt][1];
            s0 += __shfl_xor_sync(0xffffffffu, s0, 1);
            s0 += __shfl_xor_sync(0xffffffffu, s0, 2);
            s1 += __shfl_xor_sync(0xffffffffu, s1, 1);
            s1 += __shfl_xor_sync(0xffffffffu, s1, 2);
            if ((l & 3) == 0) {
                atomicAdd(&spsum[mbase + mt * 16 + g], s0);
                atomicAdd(&spsum[mbase + mt * 16 + g + 8], s1);
            }
        }
        __syncthreads();
        if (tid < 128) sinv[tid] = 1.0f / spsum[tid];
        __syncthreads();
    }

    // ================= PHASE 2: out = p@V * inv, attn = p * inv ===============
    {
        constexpr uint32_t BSZ = 36864, AP = 0, VHI = 18432, VLO = 27648;

        const uint4* P4 = (const uint4*)(pbase + (size_t)m0 * SEQ);
        const uint4* Vh4 = (const uint4*)(g_vt_hi + (size_t)bh * DIM * SEQ);
        const uint4* Vl4 = (const uint4*)(g_vt_lo + (size_t)bh * DIM * SEQ);

        const int ar0 = tid >> 3, ac = tid & 7;

        auto issue_chunk = [&](int kt, uint32_t base) {
            #pragma unroll
            for (int p = 0; p < 4; p++) {
                int r = ar0 + p * 32;
                uint32_t off = (uint32_t)(r * RS + ac * 8) * 2;
                size_t gi = (size_t)r * 256 + kt * 8 + ac;
                cp16(sb + base + AP + off, P4 + gi);
            }
            #pragma unroll
            for (int p = 0; p < 2; p++) {
                int n = ar0 + p * 32;
                uint32_t off = (uint32_t)(n * RS + ac * 8) * 2;
                size_t gi = (size_t)n * 256 + kt * 8 + ac;
                cp16(sb + base + VHI + off, Vh4 + gi);
                cp16(sb + base + VLO + off, Vl4 + gi);
            }
        };

        issue_chunk(0, 0);
        CP_COMMIT;
        CP_WAIT0;
        __syncthreads();

        const int wm = wid >> 1, wn = wid & 1;
        const int mbase = wm * 32, nbase = wn * 32;

        float acc[2][4][4];
        #pragma unroll
        for (int a = 0; a < 2; a++)
            #pragma unroll
            for (int b = 0; b < 4; b++)
                #pragma unroll
                for (int c = 0; c < 4; c++) acc[a][b][c] = 0.f;

        float* arow = attn + ((size_t)bh * SEQ + m0) * SEQ;

        for (int kt = 0; kt < 32; kt++) {
            if (kt + 1 < 32) {
                issue_chunk(kt + 1, (uint32_t)((kt + 1) & 1) * BSZ);
                CP_COMMIT;
            }
            const uint32_t base = (uint32_t)(kt & 1) * BSZ;

            // stream normalized fp32 attn from this chunk's smem copy of p
            #pragma unroll
            for (int p = 0; p < 4; p++) {
                int r = ar0 + p * 32;
                uint32_t off = (uint32_t)(r * RS + ac * 8) * 2;
                uint4 hh = *(const uint4*)(sm + base + AP + off);
                float iv = sinv[r];
                const __half2* hp = (const __half2*)&hh;
                float2 a0 = __half22float2(hp[0]);
                float2 a1 = __half22float2(hp[1]);
                float2 a2 = __half22float2(hp[2]);
                float2 a3 = __half22float2(hp[3]);
                size_t o = (size_t)r * SEQ + kt * 64 + ac * 8;
                *(float4*)&arow[o]     = make_float4(a0.x * iv, a0.y * iv, a1.x * iv, a1.y * iv);
                *(float4*)&arow[o + 4] = make_float4(a2.x * iv, a2.y * iv, a3.x * iv, a3.y * iv);
            }

            #pragma unroll
            for (int ks = 0; ks < 4; ks++) {
                uint32_t ah[2][4];
                #pragma unroll
                for (int mt = 0; mt < 2; mt++) {
                    int row = mbase + mt * 16 + arow_lane;
                    uint32_t off = (uint32_t)(row * RS) * 2 + (akc + ks * 16) * 2;
                    ldsm_x4(ah[mt], sb + base + AP + off);
                }
                #pragma unroll
                for (int nt = 0; nt < 4; nt++) {
                    int rowN = nbase + nt * 8 + lr;
                    uint32_t off = (uint32_t)(rowN * RS) * 2 + (bkc + ks * 16) * 2;
                    uint32_t vhf[2], vlf[2];
                    ldsm_x2(vhf, sb + base + VHI + off);
                    ldsm_x2(vlf, sb + base + VLO + off);
                    #pragma unroll
                    for (int mt = 0; mt < 2; mt++) {
                        mma16816h(acc[mt][nt], ah[mt], vhf);
                        mma16816h(acc[mt][nt], ah[mt], vlf);
                    }
                }
            }

            if (kt + 1 < 32) CP_WAIT0;
            __syncthreads();
        }

        float* ob = out + ((size_t)bh * SEQ + m0) * DIM;
        #pragma unroll
        for (int mt = 0; mt < 2; mt++) {
            int rl = mbase + mt * 16 + g;
            float iv0 = sinv[rl], iv1 = sinv[rl + 8];
            #pragma unroll
            for (int nt = 0; nt < 4; nt++) {
                int col = nbase + nt * 8 + q2;
                *(float2*)&ob[(size_t)rl * DIM + col] =
                    make_float2(acc[mt][nt][0] * iv0, acc[mt][nt][1] * iv0);
                *(float2*)&ob[(size_t)(rl + 8) * DIM + col] =
                    make_float2(acc[mt][nt][2] * iv1, acc[mt][nt][3] * iv1);
            }
        }
    }
}

// ---------------- launch ----------------
extern "C" void kernel_launch(void* const* d_in, const int* in_sizes, int n_in,
                              void* d_out, int out_size) {
    const float* Q    = (const float*)d_in[0];
    const float* K    = (const float*)d_in[1];
    const float* V    = (const float*)d_in[2];
    const int*   mask = (const int*)d_in[3];

    float* out  = (float*)d_out;                      // [B,H,S,D]
    float* attn = out + (size_t)NBH * SEQ * DIM;      // [B,H,S,S]

    constexpr int STRIP_SMEM = 110592;
    cudaFuncSetAttribute(fused_strip, cudaFuncAttributeMaxDynamicSharedMemorySize, STRIP_SMEM);

    mask_compress<<<SEQ * (SEQ / 32) / 256, 256>>>(mask);

    dim3 gs((unsigned)((size_t)NBH * SEQ * DIM / 4 / 256), 2);
    split_prep2<<<gs, 256>>>(Q, K);

    dim3 g0(SEQ / 128, NBH);
    vt_prep<<<g0, 256>>>(V);

    dim3 g1(SEQ / 128, NBH);
    fused_strip<<<g1, 256, STRIP_SMEM>>>(attn, out);
}

// round 14
// speedup vs baseline: 1.8700x; 1.0744x over previous
#include <cuda_runtime.h>
#include <cuda_bf16.h>
#include <cuda_fp16.h>
#include <cstdint>

#define SEQ 2048
#define DIM 64
#define NBH 32   // B*H
#define RS 72    // smem row stride in 16-bit elems (144B, conflict-free ldmatrix)

// Scratch (device globals; no allocs allowed)
__device__ __nv_bfloat16 g_qh[(size_t)NBH * SEQ * DIM];
__device__ __nv_bfloat16 g_ql[(size_t)NBH * SEQ * DIM];
__device__ __nv_bfloat16 g_kh[(size_t)NBH * SEQ * DIM];
__device__ __nv_bfloat16 g_kl[(size_t)NBH * SEQ * DIM];
__device__ __half g_vt[(size_t)NBH * DIM * SEQ];      // transposed V, fp16
__device__ __half g_p[(size_t)NBH * SEQ * SEQ];       // unnormalized exp(s), fp16
__device__ uint32_t g_mbits[(size_t)SEQ * (SEQ / 32)];

// ---------------- helpers ----------------
__device__ __forceinline__ uint32_t smem_u32(const void* p) {
    uint32_t a;
    asm("{ .reg .u64 t; cvta.to.shared.u64 t, %1; cvt.u32.u64 %0, t; }" : "=r"(a) : "l"(p));
    return a;
}
__device__ __forceinline__ void ldsm_x4(uint32_t r[4], uint32_t addr) {
    asm volatile("ldmatrix.sync.aligned.m8n8.x4.shared.b16 {%0,%1,%2,%3}, [%4];"
        : "=r"(r[0]), "=r"(r[1]), "=r"(r[2]), "=r"(r[3]) : "r"(addr));
}
__device__ __forceinline__ void ldsm_x2(uint32_t r[2], uint32_t addr) {
    asm volatile("ldmatrix.sync.aligned.m8n8.x2.shared.b16 {%0,%1}, [%2];"
        : "=r"(r[0]), "=r"(r[1]) : "r"(addr));
}
__device__ __forceinline__ void mma16816(float c[4], const uint32_t a[4], const uint32_t b[2]) {
    asm volatile(
        "mma.sync.aligned.m16n8k16.row.col.f32.bf16.bf16.f32 "
        "{%0,%1,%2,%3}, {%4,%5,%6,%7}, {%8,%9}, {%0,%1,%2,%3};"
        : "+f"(c[0]), "+f"(c[1]), "+f"(c[2]), "+f"(c[3])
        : "r"(a[0]), "r"(a[1]), "r"(a[2]), "r"(a[3]), "r"(b[0]), "r"(b[1]));
}
__device__ __forceinline__ void mma16816h(float c[4], const uint32_t a[4], const uint32_t b[2]) {
    asm volatile(
        "mma.sync.aligned.m16n8k16.row.col.f32.f16.f16.f32 "
        "{%0,%1,%2,%3}, {%4,%5,%6,%7}, {%8,%9}, {%0,%1,%2,%3};"
        : "+f"(c[0]), "+f"(c[1]), "+f"(c[2]), "+f"(c[3])
        : "r"(a[0]), "r"(a[1]), "r"(a[2]), "r"(a[3]), "r"(b[0]), "r"(b[1]));
}
__device__ __forceinline__ void cp16(uint32_t dst, const void* src) {
    asm volatile("{ .reg .u64 g; cvta.to.global.u64 g, %1; cp.async.cg.shared.global [%0], [g], 16; }"
        :: "r"(dst), "l"(src) : "memory");
}
#define CP_COMMIT asm volatile("cp.async.commit_group;" ::: "memory")
#define CP_WAIT0  asm volatile("cp.async.wait_group 0;" ::: "memory")

// streaming float4 store (evict-first: don't pollute L2 with attn output)
__device__ __forceinline__ void stcs4(float* p, float4 v) {
    asm volatile("{ .reg .u64 g; cvta.to.global.u64 g, %0; st.global.cs.v4.f32 [g], {%1,%2,%3,%4}; }"
        :: "l"(p), "f"(v.x), "f"(v.y), "f"(v.z), "f"(v.w) : "memory");
}

__device__ __forceinline__ void split4(float4 v, uint32_t& h01, uint32_t& h23,
                                       uint32_t& l01, uint32_t& l23) {
    __nv_bfloat16 h0 = __float2bfloat16_rn(v.x);
    __nv_bfloat16 h1 = __float2bfloat16_rn(v.y);
    __nv_bfloat16 h2 = __float2bfloat16_rn(v.z);
    __nv_bfloat16 h3 = __float2bfloat16_rn(v.w);
    __nv_bfloat16 q0 = __float2bfloat16_rn(v.x - __bfloat162float(h0));
    __nv_bfloat16 q1 = __float2bfloat16_rn(v.y - __bfloat162float(h1));
    __nv_bfloat16 q2 = __float2bfloat16_rn(v.z - __bfloat162float(h2));
    __nv_bfloat16 q3 = __float2bfloat16_rn(v.w - __bfloat162float(h3));
    h01 = (uint32_t)__bfloat16_as_ushort(h0) | ((uint32_t)__bfloat16_as_ushort(h1) << 16);
    h23 = (uint32_t)__bfloat16_as_ushort(h2) | ((uint32_t)__bfloat16_as_ushort(h3) << 16);
    l01 = (uint32_t)__bfloat16_as_ushort(q0) | ((uint32_t)__bfloat16_as_ushort(q1) << 16);
    l23 = (uint32_t)__bfloat16_as_ushort(q2) | ((uint32_t)__bfloat16_as_ushort(q3) << 16);
}

// ---------------- Kernel A: mask -> bitmask ----------------
__global__ __launch_bounds__(256) void mask_compress(const int* __restrict__ mask) {
    int w = blockIdx.x * 256 + threadIdx.x;
    const int4* m4 = (const int4*)mask + (size_t)w * 8;
    uint32_t b = 0;
    #pragma unroll
    for (int i = 0; i < 8; i++) {
        int4 v = m4[i];
        b |= (uint32_t)(v.x != 0) << (i * 4 + 0);
        b |= (uint32_t)(v.y != 0) << (i * 4 + 1);
        b |= (uint32_t)(v.z != 0) << (i * 4 + 2);
        b |= (uint32_t)(v.w != 0) << (i * 4 + 3);
    }
    g_mbits[w] = b;
}

// ---------------- Kernel B: fp32 -> bf16 hi/lo (Q and K in one launch) ------
__global__ __launch_bounds__(256) void split_prep2(const float* __restrict__ Q,
                                                   const float* __restrict__ K) {
    size_t i = (size_t)blockIdx.x * 256 + threadIdx.x;
    const float* X = blockIdx.y ? K : Q;
    float scale = blockIdx.y ? 1.0f : 0.125f;
    __nv_bfloat16* hi = blockIdx.y ? g_kh : g_qh;
    __nv_bfloat16* lo = blockIdx.y ? g_kl : g_ql;
    float4 v = ((const float4*)X)[i];
    v.x *= scale; v.y *= scale; v.z *= scale; v.w *= scale;
    uint32_t h01, h23, l01, l23;
    split4(v, h01, h23, l01, l23);
    ((uint2*)hi)[i] = make_uint2(h01, h23);
    ((uint2*)lo)[i] = make_uint2(l01, l23);
}

// ---------------- Kernel C: V -> Vt (single fp16, [bh][n][k]) ---------------
__global__ __launch_bounds__(256) void vt_prep(const float* __restrict__ V) {
    __shared__ float tile[128][DIM + 1];
    const int bh = blockIdx.y;
    const int k0 = blockIdx.x * 128;
    const int tid = threadIdx.x;

    const float4* V4 = (const float4*)(V + ((size_t)bh * SEQ + k0) * DIM);
    #pragma unroll
    for (int p = 0; p < 8; p++) {
        int lin = tid + p * 256;
        int r = lin >> 4, j = lin & 15;
        float4 v = V4[lin];
        tile[r][j * 4 + 0] = v.x; tile[r][j * 4 + 1] = v.y;
        tile[r][j * 4 + 2] = v.z; tile[r][j * 4 + 3] = v.w;
    }
    __syncthreads();
    #pragma unroll
    for (int p = 0; p < 32; p++) {
        int lin = tid + p * 256;
        int n = lin >> 7, k = lin & 127;
        size_t o = ((size_t)bh * DIM + n) * SEQ + k0 + k;
        g_vt[o] = __float2half_rn(tile[k][n]);
    }
}

// ---------------- Fused strip kernel -----------------------------------------
// Phase 1 smem: Q hi [0,18432) Q lo [18432,36864), K dbuf [36864,110592)
// Phase 2 smem: per buf { p fp16 [0,18432), V fp16 [18432,27648) } x2 (55296 total)
__global__ __launch_bounds__(256, 2) void fused_strip(float* __restrict__ attn,
                                                      float* __restrict__ out) {
    extern __shared__ char sm[];
    __shared__ float spsum[128];
    __shared__ float sinv[128];
    const uint32_t sb = smem_u32(sm);
    const int tid = threadIdx.x, wid = tid >> 5, l = tid & 31;
    const int m0 = blockIdx.x * 128, bh = blockIdx.y;

    if (tid < 128) spsum[tid] = 0.f;

    const int lr = l & 7, sub = l >> 3;
    const int arow_lane = lr + (sub & 1) * 8;
    const uint32_t akc = (uint32_t)((sub >> 1) * 8);
    const uint32_t bkc = (uint32_t)((sub & 1) * 8);
    const int g = l >> 2, q2 = (l & 3) * 2;

    __half* pbase = g_p + (size_t)bh * SEQ * SEQ;

    // ================= PHASE 1: QK + exp + p store (fp16) + row sums ==========
    {
        constexpr uint32_t QHI = 0, QLO = 18432, KB = 36864, KBSZ = 36864;

        const uint4* Qh4 = (const uint4*)(g_qh + ((size_t)bh * SEQ + m0) * DIM);
        const uint4* Ql4 = (const uint4*)(g_ql + ((size_t)bh * SEQ + m0) * DIM);
        const uint4* Kh4 = (const uint4*)(g_kh + (size_t)bh * SEQ * DIM);
        const uint4* Kl4 = (const uint4*)(g_kl + (size_t)bh * SEQ * DIM);

        auto issue_k = [&](int kt, uint32_t dbase) {
            const uint4* kh = Kh4 + (size_t)kt * 1024;
            const uint4* kl = Kl4 + (size_t)kt * 1024;
            #pragma unroll
            for (int p = 0; p < 4; p++) {
                int lin = tid + p * 256;
                int r = lin >> 3, c = lin & 7;
                uint32_t off = (uint32_t)(r * RS + c * 8) * 2;
                cp16(dbase + off, kh + lin);
                cp16(dbase + 18432 + off, kl + lin);
            }
        };

        #pragma unroll
        for (int p = 0; p < 4; p++) {
            int lin = tid + p * 256;
            int r = lin >> 3, c = lin & 7;
            uint32_t off = (uint32_t)(r * RS + c * 8) * 2;
            cp16(sb + QHI + off, Qh4 + lin);
            cp16(sb + QLO + off, Ql4 + lin);
        }
        CP_COMMIT;
        issue_k(0, sb + KB);
        CP_COMMIT;
        CP_WAIT0;
        __syncthreads();

        const int wm = wid >> 2, wn = wid & 3;
        const int mbase = wm * 64, nbase = wn * 32;

        float rs[4][2] = {};

        for (int kt = 0; kt < 16; kt++) {
            if (kt + 1 < 16) {
                issue_k(kt + 1, sb + KB + (uint32_t)((kt + 1) & 1) * KBSZ);
                CP_COMMIT;
            }
            const uint32_t KHIb = sb + KB + (uint32_t)(kt & 1) * KBSZ;
            const uint32_t KLOb = KHIb + 18432;

            float acc[4][4][4];
            #pragma unroll
            for (int a = 0; a < 4; a++)
                #pragma unroll
                for (int b = 0; b < 4; b++)
                    #pragma unroll
                    for (int c = 0; c < 4; c++) acc[a][b][c] = 0.f;

            #pragma unroll
            for (int ks = 0; ks < 4; ks++) {
                uint32_t ah[4][4], al[4][4];
                #pragma unroll
                for (int mt = 0; mt < 4; mt++) {
                    int row = mbase + mt * 16 + arow_lane;
                    uint32_t off = (uint32_t)(row * RS) * 2 + (akc + ks * 16) * 2;
                    ldsm_x4(ah[mt], sb + QHI + off);
                    ldsm_x4(al[mt], sb + QLO + off);
                }
                #pragma unroll
                for (int nt = 0; nt < 4; nt++) {
                    int rowN = nbase + nt * 8 + lr;
                    uint32_t off = (uint32_t)(rowN * RS) * 2 + (bkc + ks * 16) * 2;
                    uint32_t bhf[2], blf[2];
                    ldsm_x2(bhf, KHIb + off);
                    ldsm_x2(blf, KLOb + off);
                    #pragma unroll
                    for (int mt = 0; mt < 4; mt++) {
                        mma16816(acc[mt][nt], ah[mt], bhf);
                        mma16816(acc[mt][nt], ah[mt], blf);
                        mma16816(acc[mt][nt], al[mt], bhf);
                    }
                }
            }

            #pragma unroll
            for (int mt = 0; mt < 4; mt++) {
                int rl0 = mbase + mt * 16 + g;
                int row0 = m0 + rl0;
                uint32_t w0 = g_mbits[(size_t)row0 * 64 + kt * 4 + wn];
                uint32_t w1 = g_mbits[(size_t)(row0 + 8) * 64 + kt * 4 + wn];
                #pragma unroll
                for (int nt = 0; nt < 4; nt++) {
                    int cb = nt * 8 + q2;
                    float e0 = ((w0 >> cb) & 1)       ? __expf(acc[mt][nt][0]) : 0.f;
                    float e1 = ((w0 >> (cb + 1)) & 1) ? __expf(acc[mt][nt][1]) : 0.f;
                    float e2 = ((w1 >> cb) & 1)       ? __expf(acc[mt][nt][2]) : 0.f;
                    float e3 = ((w1 >> (cb + 1)) & 1) ? __expf(acc[mt][nt][3]) : 0.f;
                    rs[mt][0] += e0 + e1;
                    rs[mt][1] += e2 + e3;
                    size_t o0 = (size_t)row0 * SEQ + kt * 128 + nbase + cb;
                    size_t o1 = o0 + (size_t)8 * SEQ;
                    *(__half2*)&pbase[o0] = __floats2half2_rn(e0, e1);
                    *(__half2*)&pbase[o1] = __floats2half2_rn(e2, e3);
                }
            }

            if (kt + 1 < 16) CP_WAIT0;
            __syncthreads();
        }

        #pragma unroll
        for (int mt = 0; mt < 4; mt++) {
            float s0 = rs[mt][0], s1 = rs[mt][1];
            s0 += __shfl_xor_sync(0xffffffffu, s0, 1);
            s0 += __shfl_xor_sync(0xffffffffu, s0, 2);
            s1 += __shfl_xor_sync(0xffffffffu, s1, 1);
            s1 += __shfl_xor_sync(0xffffffffu, s1, 2);
            if ((l & 3) == 0) {
                atomicAdd(&spsum[mbase + mt * 16 + g], s0);
                atomicAdd(&spsum[mbase + mt * 16 + g + 8], s1);
            }
        }
        __syncthreads();
        if (tid < 128) sinv[tid] = 1.0f / spsum[tid];
        __syncthreads();
    }

    // ================= PHASE 2: out = p@V * inv, attn = p * inv ===============
    {
        constexpr uint32_t BSZ = 27648, AP = 0, VHI = 18432;

        const uint4* P4 = (const uint4*)(pbase + (size_t)m0 * SEQ);
        const uint4* Vh4 = (const uint4*)(g_vt + (size_t)bh * DIM * SEQ);

        const int ar0 = tid >> 3, ac = tid & 7;

        auto issue_chunk = [&](int kt, uint32_t base) {
            #pragma unroll
            for (int p = 0; p < 4; p++) {
                int r = ar0 + p * 32;
                uint32_t off = (uint32_t)(r * RS + ac * 8) * 2;
                size_t gi = (size_t)r * 256 + kt * 8 + ac;
                cp16(sb + base + AP + off, P4 + gi);
            }
            #pragma unroll
            for (int p = 0; p < 2; p++) {
                int n = ar0 + p * 32;
                uint32_t off = (uint32_t)(n * RS + ac * 8) * 2;
                size_t gi = (size_t)n * 256 + kt * 8 + ac;
                cp16(sb + base + VHI + off, Vh4 + gi);
            }
        };

        issue_chunk(0, 0);
        CP_COMMIT;
        CP_WAIT0;
        __syncthreads();

        const int wm = wid >> 1, wn = wid & 1;
        const int mbase = wm * 32, nbase = wn * 32;

        float acc[2][4][4];
        #pragma unroll
        for (int a = 0; a < 2; a++)
            #pragma unroll
            for (int b = 0; b < 4; b++)
                #pragma unroll
                for (int c = 0; c < 4; c++) acc[a][b][c] = 0.f;

        float* arow = attn + ((size_t)bh * SEQ + m0) * SEQ;

        for (int kt = 0; kt < 32; kt++) {
            if (kt + 1 < 32) {
                issue_chunk(kt + 1, (uint32_t)((kt + 1) & 1) * BSZ);
                CP_COMMIT;
            }
            const uint32_t base = (uint32_t)(kt & 1) * BSZ;

            // stream normalized fp32 attn from this chunk's smem copy of p
            #pragma unroll
            for (int p = 0; p < 4; p++) {
                int r = ar0 + p * 32;
                uint32_t off = (uint32_t)(r * RS + ac * 8) * 2;
                uint4 hh = *(const uint4*)(sm + base + AP + off);
                float iv = sinv[r];
                const __half2* hp = (const __half2*)&hh;
                float2 a0 = __half22float2(hp[0]);
                float2 a1 = __half22float2(hp[1]);
                float2 a2 = __half22float2(hp[2]);
                float2 a3 = __half22float2(hp[3]);
                size_t o = (size_t)r * SEQ + kt * 64 + ac * 8;
                stcs4(&arow[o],     make_float4(a0.x * iv, a0.y * iv, a1.x * iv, a1.y * iv));
                stcs4(&arow[o + 4], make_float4(a2.x * iv, a2.y * iv, a3.x * iv, a3.y * iv));
            }

            #pragma unroll
            for (int ks = 0; ks < 4; ks++) {
                uint32_t ah[2][4];
                #pragma unroll
                for (int mt = 0; mt < 2; mt++) {
                    int row = mbase + mt * 16 + arow_lane;
                    uint32_t off = (uint32_t)(row * RS) * 2 + (akc + ks * 16) * 2;
                    ldsm_x4(ah[mt], sb + base + AP + off);
                }
                #pragma unroll
                for (int nt = 0; nt < 4; nt++) {
                    int rowN = nbase + nt * 8 + lr;
                    uint32_t off = (uint32_t)(rowN * RS) * 2 + (bkc + ks * 16) * 2;
                    uint32_t vhf[2];
                    ldsm_x2(vhf, sb + base + VHI + off);
                    #pragma unroll
                    for (int mt = 0; mt < 2; mt++) {
                        mma16816h(acc[mt][nt], ah[mt], vhf);
                    }
                }
            }

            if (kt + 1 < 32) CP_WAIT0;
            __syncthreads();
        }

        float* ob = out + ((size_t)bh * SEQ + m0) * DIM;
        #pragma unroll
        for (int mt = 0; mt < 2; mt++) {
            int rl = mbase + mt * 16 + g;
            float iv0 = sinv[rl], iv1 = sinv[rl + 8];
            #pragma unroll
            for (int nt = 0; nt < 4; nt++) {
                int col = nbase + nt * 8 + q2;
                *(float2*)&ob[(size_t)rl * DIM + col] =
                    make_float2(acc[mt][nt][0] * iv0, acc[mt][nt][1] * iv0);
                *(float2*)&ob[(size_t)(rl + 8) * DIM + col] =
                    make_float2(acc[mt][nt][2] * iv1, acc[mt][nt][3] * iv1);
            }
        }
    }
}

// ---------------- launch ----------------
extern "C" void kernel_launch(void* const* d_in, const int* in_sizes, int n_in,
                              void* d_out, int out_size) {
    const float* Q    = (const float*)d_in[0];
    const float* K    = (const float*)d_in[1];
    const float* V    = (const float*)d_in[2];
    const int*   mask = (const int*)d_in[3];

    float* out  = (float*)d_out;                      // [B,H,S,D]
    float* attn = out + (size_t)NBH * SEQ * DIM;      // [B,H,S,S]

    constexpr int STRIP_SMEM = 110592;
    cudaFuncSetAttribute(fused_strip, cudaFuncAttributeMaxDynamicSharedMemorySize, STRIP_SMEM);

    mask_compress<<<SEQ * (SEQ / 32) / 256, 256>>>(mask);

    dim3 gs((unsigned)((size_t)NBH * SEQ * DIM / 4 / 256), 2);
    split_prep2<<<gs, 256>>>(Q, K);

    dim3 g0(SEQ / 128, NBH);
    vt_prep<<<g0, 256>>>(V);

    dim3 g1(SEQ / 128, NBH);
    fused_strip<<<g1, 256, STRIP_SMEM>>>(attn, out);
}

// round 15
// speedup vs baseline: 1.8899x; 1.0107x over previous
#include <cuda_runtime.h>
#include <cuda_bf16.h>
#include <cuda_fp16.h>
#include <cstdint>

#define SEQ 2048
#define DIM 64
#define NBH 32   // B*H
#define RS 72    // smem row stride (16-bit elems) for 64-col tiles
#define RS2 136  // smem row stride (16-bit elems) for 128-col tiles

// Scratch (device globals; no allocs allowed)
__device__ __nv_bfloat16 g_qh[(size_t)NBH * SEQ * DIM];
__device__ __nv_bfloat16 g_ql[(size_t)NBH * SEQ * DIM];
__device__ __nv_bfloat16 g_kh[(size_t)NBH * SEQ * DIM];
__device__ __nv_bfloat16 g_kl[(size_t)NBH * SEQ * DIM];
__device__ __half g_vt[(size_t)NBH * DIM * SEQ];      // transposed V, fp16
__device__ __half g_p[(size_t)NBH * SEQ * SEQ];       // unnormalized exp(s), fp16
__device__ uint32_t g_mbits[(size_t)SEQ * (SEQ / 32)];

// ---------------- helpers ----------------
__device__ __forceinline__ uint32_t smem_u32(const void* p) {
    uint32_t a;
    asm("{ .reg .u64 t; cvta.to.shared.u64 t, %1; cvt.u32.u64 %0, t; }" : "=r"(a) : "l"(p));
    return a;
}
__device__ __forceinline__ void ldsm_x4(uint32_t r[4], uint32_t addr) {
    asm volatile("ldmatrix.sync.aligned.m8n8.x4.shared.b16 {%0,%1,%2,%3}, [%4];"
        : "=r"(r[0]), "=r"(r[1]), "=r"(r[2]), "=r"(r[3]) : "r"(addr));
}
__device__ __forceinline__ void mma16816(float c[4], const uint32_t a[4], uint32_t b0, uint32_t b1) {
    asm volatile(
        "mma.sync.aligned.m16n8k16.row.col.f32.bf16.bf16.f32 "
        "{%0,%1,%2,%3}, {%4,%5,%6,%7}, {%8,%9}, {%0,%1,%2,%3};"
        : "+f"(c[0]), "+f"(c[1]), "+f"(c[2]), "+f"(c[3])
        : "r"(a[0]), "r"(a[1]), "r"(a[2]), "r"(a[3]), "r"(b0), "r"(b1));
}
__device__ __forceinline__ void mma16816h(float c[4], const uint32_t a[4], uint32_t b0, uint32_t b1) {
    asm volatile(
        "mma.sync.aligned.m16n8k16.row.col.f32.f16.f16.f32 "
        "{%0,%1,%2,%3}, {%4,%5,%6,%7}, {%8,%9}, {%0,%1,%2,%3};"
        : "+f"(c[0]), "+f"(c[1]), "+f"(c[2]), "+f"(c[3])
        : "r"(a[0]), "r"(a[1]), "r"(a[2]), "r"(a[3]), "r"(b0), "r"(b1));
}
__device__ __forceinline__ void cp16(uint32_t dst, const void* src) {
    asm volatile("{ .reg .u64 g; cvta.to.global.u64 g, %1; cp.async.cg.shared.global [%0], [g], 16; }"
        :: "r"(dst), "l"(src) : "memory");
}
#define CP_COMMIT asm volatile("cp.async.commit_group;" ::: "memory")
#define CP_WAIT0  asm volatile("cp.async.wait_group 0;" ::: "memory")

// streaming float4 store (evict-first)
__device__ __forceinline__ void stcs4(float* p, float4 v) {
    asm volatile("{ .reg .u64 g; cvta.to.global.u64 g, %0; st.global.cs.v4.f32 [g], {%1,%2,%3,%4}; }"
        :: "l"(p), "f"(v.x), "f"(v.y), "f"(v.z), "f"(v.w) : "memory");
}

__device__ __forceinline__ void split4(float4 v, uint32_t& h01, uint32_t& h23,
                                       uint32_t& l01, uint32_t& l23) {
    __nv_bfloat16 h0 = __float2bfloat16_rn(v.x);
    __nv_bfloat16 h1 = __float2bfloat16_rn(v.y);
    __nv_bfloat16 h2 = __float2bfloat16_rn(v.z);
    __nv_bfloat16 h3 = __float2bfloat16_rn(v.w);
    __nv_bfloat16 q0 = __float2bfloat16_rn(v.x - __bfloat162float(h0));
    __nv_bfloat16 q1 = __float2bfloat16_rn(v.y - __bfloat162float(h1));
    __nv_bfloat16 q2 = __float2bfloat16_rn(v.z - __bfloat162float(h2));
    __nv_bfloat16 q3 = __float2bfloat16_rn(v.w - __bfloat162float(h3));
    h01 = (uint32_t)__bfloat16_as_ushort(h0) | ((uint32_t)__bfloat16_as_ushort(h1) << 16);
    h23 = (uint32_t)__bfloat16_as_ushort(h2) | ((uint32_t)__bfloat16_as_ushort(h3) << 16);
    l01 = (uint32_t)__bfloat16_as_ushort(q0) | ((uint32_t)__bfloat16_as_ushort(q1) << 16);
    l23 = (uint32_t)__bfloat16_as_ushort(q2) | ((uint32_t)__bfloat16_as_ushort(q3) << 16);
}

// ---------------- Kernel A: mask -> bitmask ----------------
__global__ __launch_bounds__(256) void mask_compress(const int* __restrict__ mask) {
    int w = blockIdx.x * 256 + threadIdx.x;
    const int4* m4 = (const int4*)mask + (size_t)w * 8;
    uint32_t b = 0;
    #pragma unroll
    for (int i = 0; i < 8; i++) {
        int4 v = m4[i];
        b |= (uint32_t)(v.x != 0) << (i * 4 + 0);
        b |= (uint32_t)(v.y != 0) << (i * 4 + 1);
        b |= (uint32_t)(v.z != 0) << (i * 4 + 2);
        b |= (uint32_t)(v.w != 0) << (i * 4 + 3);
    }
    g_mbits[w] = b;
}

// ---------------- Kernel B: fp32 -> bf16 hi/lo (Q and K in one launch) ------
__global__ __launch_bounds__(256) void split_prep2(const float* __restrict__ Q,
                                                   const float* __restrict__ K) {
    size_t i = (size_t)blockIdx.x * 256 + threadIdx.x;
    const float* X = blockIdx.y ? K : Q;
    float scale = blockIdx.y ? 1.0f : 0.125f;
    __nv_bfloat16* hi = blockIdx.y ? g_kh : g_qh;
    __nv_bfloat16* lo = blockIdx.y ? g_kl : g_ql;
    float4 v = ((const float4*)X)[i];
    v.x *= scale; v.y *= scale; v.z *= scale; v.w *= scale;
    uint32_t h01, h23, l01, l23;
    split4(v, h01, h23, l01, l23);
    ((uint2*)hi)[i] = make_uint2(h01, h23);
    ((uint2*)lo)[i] = make_uint2(l01, l23);
}

// ---------------- Kernel C: V -> Vt (single fp16, [bh][n][k]) ---------------
__global__ __launch_bounds__(256) void vt_prep(const float* __restrict__ V) {
    __shared__ float tile[128][DIM + 1];
    const int bh = blockIdx.y;
    const int k0 = blockIdx.x * 128;
    const int tid = threadIdx.x;

    const float4* V4 = (const float4*)(V + ((size_t)bh * SEQ + k0) * DIM);
    #pragma unroll
    for (int p = 0; p < 8; p++) {
        int lin = tid + p * 256;
        int r = lin >> 4, j = lin & 15;
        float4 v = V4[lin];
        tile[r][j * 4 + 0] = v.x; tile[r][j * 4 + 1] = v.y;
        tile[r][j * 4 + 2] = v.z; tile[r][j * 4 + 3] = v.w;
    }
    __syncthreads();
    #pragma unroll
    for (int p = 0; p < 32; p++) {
        int lin = tid + p * 256;
        int n = lin >> 7, k = lin & 127;
        size_t o = ((size_t)bh * DIM + n) * SEQ + k0 + k;
        g_vt[o] = __float2half_rn(tile[k][n]);
    }
}

// ---------------- Fused strip kernel -----------------------------------------
// Phase 1 smem: Q hi [0,18432) Q lo [18432,36864), K dbuf [36864,110592)
// Phase 2 smem: per buf { p fp16 [0,34816), V fp16 [34816,52224) } x2 (104448 total)
__global__ __launch_bounds__(256, 2) void fused_strip(float* __restrict__ attn,
                                                      float* __restrict__ out) {
    extern __shared__ char sm[];
    __shared__ float spsum[128];
    __shared__ float sinv[128];
    const uint32_t sb = smem_u32(sm);
    const int tid = threadIdx.x, wid = tid >> 5, l = tid & 31;
    const int m0 = blockIdx.x * 128, bh = blockIdx.y;

    if (tid < 128) spsum[tid] = 0.f;

    const int lr = l & 7, sub = l >> 3;
    const int arow_lane = lr + (sub & 1) * 8;
    const uint32_t akc = (uint32_t)((sub >> 1) * 8);
    const int bro = lr + ((l >> 4) << 3);            // x4 B-frag row
    const uint32_t bkc4 = (uint32_t)(((l >> 3) & 1) * 8);
    const int g = l >> 2, q2 = (l & 3) * 2;

    __half* pbase = g_p + (size_t)bh * SEQ * SEQ;

    // ================= PHASE 1: QK + exp + p store (fp16) + row sums ==========
    {
        constexpr uint32_t QHI = 0, QLO = 18432, KB = 36864, KBSZ = 36864;

        const uint4* Qh4 = (const uint4*)(g_qh + ((size_t)bh * SEQ + m0) * DIM);
        const uint4* Ql4 = (const uint4*)(g_ql + ((size_t)bh * SEQ + m0) * DIM);
        const uint4* Kh4 = (const uint4*)(g_kh + (size_t)bh * SEQ * DIM);
        const uint4* Kl4 = (const uint4*)(g_kl + (size_t)bh * SEQ * DIM);

        auto issue_k = [&](int kt, uint32_t dbase) {
            const uint4* kh = Kh4 + (size_t)kt * 1024;
            const uint4* kl = Kl4 + (size_t)kt * 1024;
            #pragma unroll
            for (int p = 0; p < 4; p++) {
                int lin = tid + p * 256;
                int r = lin >> 3, c = lin & 7;
                uint32_t off = (uint32_t)(r * RS + c * 8) * 2;
                cp16(dbase + off, kh + lin);
                cp16(dbase + 18432 + off, kl + lin);
            }
        };

        #pragma unroll
        for (int p = 0; p < 4; p++) {
            int lin = tid + p * 256;
            int r = lin >> 3, c = lin & 7;
            uint32_t off = (uint32_t)(r * RS + c * 8) * 2;
            cp16(sb + QHI + off, Qh4 + lin);
            cp16(sb + QLO + off, Ql4 + lin);
        }
        CP_COMMIT;
        issue_k(0, sb + KB);
        CP_COMMIT;
        CP_WAIT0;
        __syncthreads();

        const int wm = wid >> 2, wn = wid & 3;
        const int mbase = wm * 64, nbase = wn * 32;

        float rs[4][2] = {};

        for (int kt = 0; kt < 16; kt++) {
            if (kt + 1 < 16) {
                issue_k(kt + 1, sb + KB + (uint32_t)((kt + 1) & 1) * KBSZ);
                CP_COMMIT;
            }
            const uint32_t KHIb = sb + KB + (uint32_t)(kt & 1) * KBSZ;
            const uint32_t KLOb = KHIb + 18432;

            float acc[4][4][4];
            #pragma unroll
            for (int a = 0; a < 4; a++)
                #pragma unroll
                for (int b = 0; b < 4; b++)
                    #pragma unroll
                    for (int c = 0; c < 4; c++) acc[a][b][c] = 0.f;

            #pragma unroll
            for (int ks = 0; ks < 4; ks++) {
                uint32_t ah[4][4], al[4][4];
                #pragma unroll
                for (int mt = 0; mt < 4; mt++) {
                    int row = mbase + mt * 16 + arow_lane;
                    uint32_t off = (uint32_t)(row * RS) * 2 + (akc + ks * 16) * 2;
                    ldsm_x4(ah[mt], sb + QHI + off);
                    ldsm_x4(al[mt], sb + QLO + off);
                }
                #pragma unroll
                for (int ntp = 0; ntp < 2; ntp++) {
                    int rowN = nbase + ntp * 16 + bro;
                    uint32_t off = (uint32_t)(rowN * RS) * 2 + (bkc4 + ks * 16) * 2;
                    uint32_t bh4[4], bl4[4];
                    ldsm_x4(bh4, KHIb + off);
                    ldsm_x4(bl4, KLOb + off);
                    #pragma unroll
                    for (int mt = 0; mt < 4; mt++) {
                        mma16816(acc[mt][2 * ntp],     ah[mt], bh4[0], bh4[1]);
                        mma16816(acc[mt][2 * ntp],     ah[mt], bl4[0], bl4[1]);
                        mma16816(acc[mt][2 * ntp],     al[mt], bh4[0], bh4[1]);
                        mma16816(acc[mt][2 * ntp + 1], ah[mt], bh4[2], bh4[3]);
                        mma16816(acc[mt][2 * ntp + 1], ah[mt], bl4[2], bl4[3]);
                        mma16816(acc[mt][2 * ntp + 1], al[mt], bh4[2], bh4[3]);
                    }
                }
            }

            #pragma unroll
            for (int mt = 0; mt < 4; mt++) {
                int rl0 = mbase + mt * 16 + g;
                int row0 = m0 + rl0;
                uint32_t w0 = g_mbits[(size_t)row0 * 64 + kt * 4 + wn];
                uint32_t w1 = g_mbits[(size_t)(row0 + 8) * 64 + kt * 4 + wn];
                #pragma unroll
                for (int nt = 0; nt < 4; nt++) {
                    int cb = nt * 8 + q2;
                    float e0 = ((w0 >> cb) & 1)       ? __expf(acc[mt][nt][0]) : 0.f;
                    float e1 = ((w0 >> (cb + 1)) & 1) ? __expf(acc[mt][nt][1]) : 0.f;
                    float e2 = ((w1 >> cb) & 1)       ? __expf(acc[mt][nt][2]) : 0.f;
                    float e3 = ((w1 >> (cb + 1)) & 1) ? __expf(acc[mt][nt][3]) : 0.f;
                    rs[mt][0] += e0 + e1;
                    rs[mt][1] += e2 + e3;
                    size_t o0 = (size_t)row0 * SEQ + kt * 128 + nbase + cb;
                    size_t o1 = o0 + (size_t)8 * SEQ;
                    *(__half2*)&pbase[o0] = __floats2half2_rn(e0, e1);
                    *(__half2*)&pbase[o1] = __floats2half2_rn(e2, e3);
                }
            }

            if (kt + 1 < 16) CP_WAIT0;
            __syncthreads();
        }

        #pragma unroll
        for (int mt = 0; mt < 4; mt++) {
            float s0 = rs[mt][0], s1 = rs[mt][1];
            s0 += __shfl_xor_sync(0xffffffffu, s0, 1);
            s0 += __shfl_xor_sync(0xffffffffu, s0, 2);
            s1 += __shfl_xor_sync(0xffffffffu, s1, 1);
            s1 += __shfl_xor_sync(0xffffffffu, s1, 2);
            if ((l & 3) == 0) {
                atomicAdd(&spsum[mbase + mt * 16 + g], s0);
                atomicAdd(&spsum[mbase + mt * 16 + g + 8], s1);
            }
        }
        __syncthreads();
        if (tid < 128) sinv[tid] = 1.0f / spsum[tid];
        __syncthreads();
    }

    // ================= PHASE 2: out = p@V * inv, attn = p * inv ===============
    // 128-wide k-chunks, 16 chunks. smem per buf: p 34816 B, V 17408 B.
    {
        constexpr uint32_t BSZ = 52224, AP = 0, VHI = 34816;

        const uint4* P4 = (const uint4*)(pbase + (size_t)m0 * SEQ);
        const uint4* Vh4 = (const uint4*)(g_vt + (size_t)bh * DIM * SEQ);

        auto issue_chunk = [&](int kt, uint32_t base) {
            #pragma unroll
            for (int p = 0; p < 8; p++) {
                int lin = tid + p * 256;
                int r = lin >> 4, c = lin & 15;
                uint32_t off = (uint32_t)(r * RS2 + c * 8) * 2;
                cp16(sb + base + AP + off, P4 + (size_t)r * 256 + kt * 16 + c);
            }
            #pragma unroll
            for (int p = 0; p < 4; p++) {
                int lin = tid + p * 256;
                int n = lin >> 4, c = lin & 15;
                uint32_t off = (uint32_t)(n * RS2 + c * 8) * 2;
                cp16(sb + base + VHI + off, Vh4 + (size_t)n * 256 + kt * 16 + c);
            }
        };

        issue_chunk(0, 0);
        CP_COMMIT;
        CP_WAIT0;
        __syncthreads();

        const int wm = wid >> 1, wn = wid & 1;
        const int mbase = wm * 32, nbase = wn * 32;

        float acc[2][4][4];
        #pragma unroll
        for (int a = 0; a < 2; a++)
            #pragma unroll
            for (int b = 0; b < 4; b++)
                #pragma unroll
                for (int c = 0; c < 4; c++) acc[a][b][c] = 0.f;

        float* arow = attn + ((size_t)bh * SEQ + m0) * SEQ;

        for (int kt = 0; kt < 16; kt++) {
            if (kt + 1 < 16) {
                issue_chunk(kt + 1, (uint32_t)((kt + 1) & 1) * BSZ);
                CP_COMMIT;
            }
            const uint32_t base = (uint32_t)(kt & 1) * BSZ;

            // MMAs first (tensor pipe starts immediately)
            #pragma unroll
            for (int ks = 0; ks < 8; ks++) {
                uint32_t ah[2][4];
                #pragma unroll
                for (int mt = 0; mt < 2; mt++) {
                    int row = mbase + mt * 16 + arow_lane;
                    uint32_t off = (uint32_t)(row * RS2) * 2 + (akc + ks * 16) * 2;
                    ldsm_x4(ah[mt], sb + base + AP + off);
                }
                #pragma unroll
                for (int ntp = 0; ntp < 2; ntp++) {
                    int rowN = nbase + ntp * 16 + bro;
                    uint32_t off = (uint32_t)(rowN * RS2) * 2 + (bkc4 + ks * 16) * 2;
                    uint32_t vh4[4];
                    ldsm_x4(vh4, sb + base + VHI + off);
                    #pragma unroll
                    for (int mt = 0; mt < 2; mt++) {
                        mma16816h(acc[mt][2 * ntp],     ah[mt], vh4[0], vh4[1]);
                        mma16816h(acc[mt][2 * ntp + 1], ah[mt], vh4[2], vh4[3]);
                    }
                }
            }

            // attn stores after MMAs (overlap next chunk's cp.async wait)
            #pragma unroll
            for (int p = 0; p < 8; p++) {
                int lin = tid + p * 256;
                int r = lin >> 4, c = lin & 15;
                uint32_t off = (uint32_t)(r * RS2 + c * 8) * 2;
                uint4 hh = *(const uint4*)(sm + base + AP + off);
                float iv = sinv[r];
                const __half2* hp = (const __half2*)&hh;
                float2 a0 = __half22float2(hp[0]);
                float2 a1 = __half22float2(hp[1]);
                float2 a2 = __half22float2(hp[2]);
                float2 a3 = __half22float2(hp[3]);
                size_t o = (size_t)r * SEQ + kt * 128 + c * 8;
                stcs4(&arow[o],     make_float4(a0.x * iv, a0.y * iv, a1.x * iv, a1.y * iv));
                stcs4(&arow[o + 4], make_float4(a2.x * iv, a2.y * iv, a3.x * iv, a3.y * iv));
            }

            if (kt + 1 < 16) CP_WAIT0;
            __syncthreads();
        }

        float* ob = out + ((size_t)bh * SEQ + m0) * DIM;
        #pragma unroll
        for (int mt = 0; mt < 2; mt++) {
            int rl = mbase + mt * 16 + g;
            float iv0 = sinv[rl], iv1 = sinv[rl + 8];
            #pragma unroll
            for (int nt = 0; nt < 4; nt++) {
                int col = nbase + nt * 8 + q2;
                *(float2*)&ob[(size_t)rl * DIM + col] =
                    make_float2(acc[mt][nt][0] * iv0, acc[mt][nt][1] * iv0);
                *(float2*)&ob[(size_t)(rl + 8) * DIM + col] =
                    make_float2(acc[mt][nt][2] * iv1, acc[mt][nt][3] * iv1);
            }
        }
    }
}

// ---------------- launch ----------------
extern "C" void kernel_launch(void* const* d_in, const int* in_sizes, int n_in,
                              void* d_out, int out_size) {
    const float* Q    = (const float*)d_in[0];
    const float* K    = (const float*)d_in[1];
    const float* V    = (const float*)d_in[2];
    const int*   mask = (const int*)d_in[3];

    float* out  = (float*)d_out;                      // [B,H,S,D]
    float* attn = out + (size_t)NBH * SEQ * DIM;      // [B,H,S,S]

    constexpr int STRIP_SMEM = 110592;
    cudaFuncSetAttribute(fused_strip, cudaFuncAttributeMaxDynamicSharedMemorySize, STRIP_SMEM);

    mask_compress<<<SEQ * (SEQ / 32) / 256, 256>>>(mask);

    dim3 gs((unsigned)((size_t)NBH * SEQ * DIM / 4 / 256), 2);
    split_prep2<<<gs, 256>>>(Q, K);

    dim3 g0(SEQ / 128, NBH);
    vt_prep<<<g0, 256>>>(V);

    dim3 g1(SEQ / 128, NBH);
    fused_strip<<<g1, 256, STRIP_SMEM>>>(attn, out);
}

// round 17
// speedup vs baseline: 2.0792x; 1.1002x over previous
#include <cuda_runtime.h>
#include <cuda_bf16.h>
#include <cuda_fp16.h>
#include <cstdint>
#include <cstring>

#define SEQ 2048
#define DIM 64
#define NBH 32   // B*H
#define RS 72    // smem row stride (16-bit elems) for 64-col tiles
#define RS2 136  // smem row stride (16-bit elems) for 128-col tiles

// Scratch (device globals; no allocs allowed)
__device__ __nv_bfloat16 g_qh[(size_t)NBH * SEQ * DIM];
__device__ __nv_bfloat16 g_ql[(size_t)NBH * SEQ * DIM];
__device__ __nv_bfloat16 g_kh[(size_t)NBH * SEQ * DIM];
__device__ __nv_bfloat16 g_kl[(size_t)NBH * SEQ * DIM];
__device__ __half g_vt[(size_t)NBH * DIM * SEQ];      // transposed V, fp16
// p in MMA-fragment order: [bh][mtile(128)][kt(16)][kpair(8)][lane(32)] uint4
__device__ uint4 g_pf[(size_t)NBH * 128 * 16 * 8 * 32];
__device__ uint32_t g_mbits[(size_t)SEQ * (SEQ / 32)];

// ---------------- helpers ----------------
__device__ __forceinline__ uint32_t h2u(__half2 h) {
    uint32_t u;
    memcpy(&u, &h, 4);
    return u;
}
__device__ __forceinline__ uint32_t smem_u32(const void* p) {
    uint32_t a;
    asm("{ .reg .u64 t; cvta.to.shared.u64 t, %1; cvt.u32.u64 %0, t; }" : "=r"(a) : "l"(p));
    return a;
}
__device__ __forceinline__ void ldsm_x4(uint32_t r[4], uint32_t addr) {
    asm volatile("ldmatrix.sync.aligned.m8n8.x4.shared.b16 {%0,%1,%2,%3}, [%4];"
        : "=r"(r[0]), "=r"(r[1]), "=r"(r[2]), "=r"(r[3]) : "r"(addr));
}
__device__ __forceinline__ void mma16816(float c[4], const uint32_t a[4], uint32_t b0, uint32_t b1) {
    asm volatile(
        "mma.sync.aligned.m16n8k16.row.col.f32.bf16.bf16.f32 "
        "{%0,%1,%2,%3}, {%4,%5,%6,%7}, {%8,%9}, {%0,%1,%2,%3};"
        : "+f"(c[0]), "+f"(c[1]), "+f"(c[2]), "+f"(c[3])
        : "r"(a[0]), "r"(a[1]), "r"(a[2]), "r"(a[3]), "r"(b0), "r"(b1));
}
__device__ __forceinline__ void mma16816h(float c[4], const uint32_t a[4], uint32_t b0, uint32_t b1) {
    asm volatile(
        "mma.sync.aligned.m16n8k16.row.col.f32.f16.f16.f32 "
        "{%0,%1,%2,%3}, {%4,%5,%6,%7}, {%8,%9}, {%0,%1,%2,%3};"
        : "+f"(c[0]), "+f"(c[1]), "+f"(c[2]), "+f"(c[3])
        : "r"(a[0]), "r"(a[1]), "r"(a[2]), "r"(a[3]), "r"(b0), "r"(b1));
}
__device__ __forceinline__ void cp16(uint32_t dst, const void* src) {
    asm volatile("{ .reg .u64 g; cvta.to.global.u64 g, %1; cp.async.cg.shared.global [%0], [g], 16; }"
        :: "r"(dst), "l"(src) : "memory");
}
#define CP_COMMIT asm volatile("cp.async.commit_group;" ::: "memory")
#define CP_WAIT0  asm volatile("cp.async.wait_group 0;" ::: "memory")

// streaming stores (evict-first; attn isn't re-read)
__device__ __forceinline__ void stcs2(float* p, float2 v) {
    asm volatile("{ .reg .u64 g; cvta.to.global.u64 g, %0; st.global.cs.v2.f32 [g], {%1,%2}; }"
        :: "l"(p), "f"(v.x), "f"(v.y) : "memory");
}

__device__ __forceinline__ void split4(float4 v, uint32_t& h01, uint32_t& h23,
                                       uint32_t& l01, uint32_t& l23) {
    __nv_bfloat16 h0 = __float2bfloat16_rn(v.x);
    __nv_bfloat16 h1 = __float2bfloat16_rn(v.y);
    __nv_bfloat16 h2 = __float2bfloat16_rn(v.z);
    __nv_bfloat16 h3 = __float2bfloat16_rn(v.w);
    __nv_bfloat16 q0 = __float2bfloat16_rn(v.x - __bfloat162float(h0));
    __nv_bfloat16 q1 = __float2bfloat16_rn(v.y - __bfloat162float(h1));
    __nv_bfloat16 q2 = __float2bfloat16_rn(v.z - __bfloat162float(h2));
    __nv_bfloat16 q3 = __float2bfloat16_rn(v.w - __bfloat162float(h3));
    h01 = (uint32_t)__bfloat16_as_ushort(h0) | ((uint32_t)__bfloat16_as_ushort(h1) << 16);
    h23 = (uint32_t)__bfloat16_as_ushort(h2) | ((uint32_t)__bfloat16_as_ushort(h3) << 16);
    l01 = (uint32_t)__bfloat16_as_ushort(q0) | ((uint32_t)__bfloat16_as_ushort(q1) << 16);
    l23 = (uint32_t)__bfloat16_as_ushort(q2) | ((uint32_t)__bfloat16_as_ushort(q3) << 16);
}

// ---------------- Kernel A: mask -> bitmask ----------------
__global__ __launch_bounds__(256) void mask_compress(const int* __restrict__ mask) {
    int w = blockIdx.x * 256 + threadIdx.x;
    const int4* m4 = (const int4*)mask + (size_t)w * 8;
    uint32_t b = 0;
    #pragma unroll
    for (int i = 0; i < 8; i++) {
        int4 v = m4[i];
        b |= (uint32_t)(v.x != 0) << (i * 4 + 0);
        b |= (uint32_t)(v.y != 0) << (i * 4 + 1);
        b |= (uint32_t)(v.z != 0) << (i * 4 + 2);
        b |= (uint32_t)(v.w != 0) << (i * 4 + 3);
    }
    g_mbits[w] = b;
}

// ---------------- Kernel B: fp32 -> bf16 hi/lo (Q and K in one launch) ------
__global__ __launch_bounds__(256) void split_prep2(const float* __restrict__ Q,
                                                   const float* __restrict__ K) {
    size_t i = (size_t)blockIdx.x * 256 + threadIdx.x;
    const float* X = blockIdx.y ? K : Q;
    float scale = blockIdx.y ? 1.0f : 0.125f;
    __nv_bfloat16* hi = blockIdx.y ? g_kh : g_qh;
    __nv_bfloat16* lo = blockIdx.y ? g_kl : g_ql;
    float4 v = ((const float4*)X)[i];
    v.x *= scale; v.y *= scale; v.z *= scale; v.w *= scale;
    uint32_t h01, h23, l01, l23;
    split4(v, h01, h23, l01, l23);
    ((uint2*)hi)[i] = make_uint2(h01, h23);
    ((uint2*)lo)[i] = make_uint2(l01, l23);
}

// ---------------- Kernel C: V -> Vt (single fp16, [bh][n][k]) ---------------
__global__ __launch_bounds__(256) void vt_prep(const float* __restrict__ V) {
    __shared__ float tile[128][DIM + 1];
    const int bh = blockIdx.y;
    const int k0 = blockIdx.x * 128;
    const int tid = threadIdx.x;

    const float4* V4 = (const float4*)(V + ((size_t)bh * SEQ + k0) * DIM);
    #pragma unroll
    for (int p = 0; p < 8; p++) {
        int lin = tid + p * 256;
        int r = lin >> 4, j = lin & 15;
        float4 v = V4[lin];
        tile[r][j * 4 + 0] = v.x; tile[r][j * 4 + 1] = v.y;
        tile[r][j * 4 + 2] = v.z; tile[r][j * 4 + 3] = v.w;
    }
    __syncthreads();
    #pragma unroll
    for (int p = 0; p < 32; p++) {
        int lin = tid + p * 256;
        int n = lin >> 7, k = lin & 127;
        size_t o = ((size_t)bh * DIM + n) * SEQ + k0 + k;
        g_vt[o] = __float2half_rn(tile[k][n]);
    }
}

// ---------------- Fused strip kernel -----------------------------------------
// Phase 1 smem: Q hi [0,18432) Q lo [18432,36864), K dbuf [36864,110592)
// Phase 2 smem: V fp16 dbuf { [0,17408), [17408,34816) }
__global__ __launch_bounds__(256, 2) void fused_strip(float* __restrict__ attn,
                                                      float* __restrict__ out) {
    extern __shared__ char sm[];
    __shared__ float spsum[128];
    __shared__ float sinv[128];
    const uint32_t sb = smem_u32(sm);
    const int tid = threadIdx.x, wid = tid >> 5, l = tid & 31;
    const int m0 = blockIdx.x * 128, bh = blockIdx.y;

    if (tid < 128) spsum[tid] = 0.f;

    const int lr = l & 7, sub = l >> 3;
    const int arow_lane = lr + (sub & 1) * 8;
    const uint32_t akc = (uint32_t)((sub >> 1) * 8);
    const int bro = lr + ((l >> 4) << 3);            // x4 B-frag row
    const uint32_t bkc4 = (uint32_t)(((l >> 3) & 1) * 8);
    const int g = l >> 2, q2 = (l & 3) * 2;

    // ================= PHASE 1: QK + exp + p frag store + row sums ============
    {
        constexpr uint32_t QHI = 0, QLO = 18432, KB = 36864, KBSZ = 36864;

        const uint4* Qh4 = (const uint4*)(g_qh + ((size_t)bh * SEQ + m0) * DIM);
        const uint4* Ql4 = (const uint4*)(g_ql + ((size_t)bh * SEQ + m0) * DIM);
        const uint4* Kh4 = (const uint4*)(g_kh + (size_t)bh * SEQ * DIM);
        const uint4* Kl4 = (const uint4*)(g_kl + (size_t)bh * SEQ * DIM);

        auto issue_k = [&](int kt, uint32_t dbase) {
            const uint4* kh = Kh4 + (size_t)kt * 1024;
            const uint4* kl = Kl4 + (size_t)kt * 1024;
            #pragma unroll
            for (int p = 0; p < 4; p++) {
                int lin = tid + p * 256;
                int r = lin >> 3, c = lin & 7;
                uint32_t off = (uint32_t)(r * RS + c * 8) * 2;
                cp16(dbase + off, kh + lin);
                cp16(dbase + 18432 + off, kl + lin);
            }
        };

        #pragma unroll
        for (int p = 0; p < 4; p++) {
            int lin = tid + p * 256;
            int r = lin >> 3, c = lin & 7;
            uint32_t off = (uint32_t)(r * RS + c * 8) * 2;
            cp16(sb + QHI + off, Qh4 + lin);
            cp16(sb + QLO + off, Ql4 + lin);
        }
        CP_COMMIT;
        issue_k(0, sb + KB);
        CP_COMMIT;
        CP_WAIT0;
        __syncthreads();

        const int wm = wid >> 2, wn = wid & 3;
        const int mbase = wm * 64, nbase = wn * 32;

        float rs[4][2] = {};

        for (int kt = 0; kt < 16; kt++) {
            if (kt + 1 < 16) {
                issue_k(kt + 1, sb + KB + (uint32_t)((kt + 1) & 1) * KBSZ);
                CP_COMMIT;
            }
            const uint32_t KHIb = sb + KB + (uint32_t)(kt & 1) * KBSZ;
            const uint32_t KLOb = KHIb + 18432;

            float acc[4][4][4];
            #pragma unroll
            for (int a = 0; a < 4; a++)
                #pragma unroll
                for (int b = 0; b < 4; b++)
                    #pragma unroll
                    for (int c = 0; c < 4; c++) acc[a][b][c] = 0.f;

            #pragma unroll
            for (int ks = 0; ks < 4; ks++) {
                uint32_t ah[4][4], al[4][4];
                #pragma unroll
                for (int mt = 0; mt < 4; mt++) {
                    int row = mbase + mt * 16 + arow_lane;
                    uint32_t off = (uint32_t)(row * RS) * 2 + (akc + ks * 16) * 2;
                    ldsm_x4(ah[mt], sb + QHI + off);
                    ldsm_x4(al[mt], sb + QLO + off);
                }
                #pragma unroll
                for (int ntp = 0; ntp < 2; ntp++) {
                    int rowN = nbase + ntp * 16 + bro;
                    uint32_t off = (uint32_t)(rowN * RS) * 2 + (bkc4 + ks * 16) * 2;
                    uint32_t bh4[4], bl4[4];
                    ldsm_x4(bh4, KHIb + off);
                    ldsm_x4(bl4, KLOb + off);
                    #pragma unroll
                    for (int mt = 0; mt < 4; mt++) {
                        mma16816(acc[mt][2 * ntp],     ah[mt], bh4[0], bh4[1]);
                        mma16816(acc[mt][2 * ntp],     ah[mt], bl4[0], bl4[1]);
                        mma16816(acc[mt][2 * ntp],     al[mt], bh4[0], bh4[1]);
                        mma16816(acc[mt][2 * ntp + 1], ah[mt], bh4[2], bh4[3]);
                        mma16816(acc[mt][2 * ntp + 1], ah[mt], bl4[2], bl4[3]);
                        mma16816(acc[mt][2 * ntp + 1], al[mt], bh4[2], bh4[3]);
                    }
                }
            }

            // epilogue: mask + exp + fragment-order p store + row sums
            #pragma unroll
            for (int mt = 0; mt < 4; mt++) {
                int rl0 = mbase + mt * 16 + g;
                int row0 = m0 + rl0;
                uint32_t w0 = g_mbits[(size_t)row0 * 64 + kt * 4 + wn];
                uint32_t w1 = g_mbits[(size_t)(row0 + 8) * 64 + kt * 4 + wn];
                int mtile = blockIdx.x * 8 + wm * 4 + mt;
                #pragma unroll
                for (int ntp = 0; ntp < 2; ntp++) {
                    uint4 st;
                    #pragma unroll
                    for (int h = 0; h < 2; h++) {
                        int nt = 2 * ntp + h;
                        int cb = nt * 8 + q2;
                        float e0 = ((w0 >> cb) & 1)       ? __expf(acc[mt][nt][0]) : 0.f;
                        float e1 = ((w0 >> (cb + 1)) & 1) ? __expf(acc[mt][nt][1]) : 0.f;
                        float e2 = ((w1 >> cb) & 1)       ? __expf(acc[mt][nt][2]) : 0.f;
                        float e3 = ((w1 >> (cb + 1)) & 1) ? __expf(acc[mt][nt][3]) : 0.f;
                        rs[mt][0] += e0 + e1;
                        rs[mt][1] += e2 + e3;
                        uint32_t h01 = h2u(__floats2half2_rn(e0, e1));
                        uint32_t h23 = h2u(__floats2half2_rn(e2, e3));
                        if (h == 0) { st.x = h01; st.y = h23; }
                        else        { st.z = h01; st.w = h23; }
                    }
                    int kp = wn * 2 + ntp;
                    g_pf[((((size_t)bh * 128 + mtile) * 16 + kt) * 8 + kp) * 32 + l] = st;
                }
            }

            if (kt + 1 < 16) CP_WAIT0;
            __syncthreads();
        }

        #pragma unroll
        for (int mt = 0; mt < 4; mt++) {
            float s0 = rs[mt][0], s1 = rs[mt][1];
            s0 += __shfl_xor_sync(0xffffffffu, s0, 1);
            s0 += __shfl_xor_sync(0xffffffffu, s0, 2);
            s1 += __shfl_xor_sync(0xffffffffu, s1, 1);
            s1 += __shfl_xor_sync(0xffffffffu, s1, 2);
            if ((l & 3) == 0) {
                atomicAdd(&spsum[mbase + mt * 16 + g], s0);
                atomicAdd(&spsum[mbase + mt * 16 + g + 8], s1);
            }
        }
        __syncthreads();
        if (tid < 128) sinv[tid] = 1.0f / spsum[tid];
        __syncthreads();
    }

    // ================= PHASE 2: out = p@V * inv, attn = p * inv ===============
    // warp wid owns m-tile (rows wid*16..+15), full n=64. A via direct LDG of frags.
    {
        constexpr uint32_t VSZ = 17408;

        const uint4* Vh4 = (const uint4*)(g_vt + (size_t)bh * DIM * SEQ);
        const uint4* pw = g_pf + (((size_t)bh * 128 + blockIdx.x * 8 + wid) * 16) * 8 * 32;

        auto issue_v = [&](int kt, uint32_t base) {
            #pragma unroll
            for (int p = 0; p < 4; p++) {
                int lin = tid + p * 256;
                int n = lin >> 4, c = lin & 15;
                uint32_t off = (uint32_t)(n * RS2 + c * 8) * 2;
                cp16(sb + base + off, Vh4 + (size_t)n * 256 + kt * 16 + c);
            }
        };

        issue_v(0, 0);
        CP_COMMIT;
        CP_WAIT0;
        __syncthreads();

        float oacc[8][4];
        #pragma unroll
        for (int a = 0; a < 8; a++)
            #pragma unroll
            for (int c = 0; c < 4; c++) oacc[a][c] = 0.f;

        const int r0 = wid * 16 + g;
        const float iv0 = sinv[r0], iv1 = sinv[r0 + 8];
        float* arow = attn + ((size_t)bh * SEQ + m0) * SEQ;

        for (int kt = 0; kt < 16; kt++) {
            if (kt + 1 < 16) {
                issue_v(kt + 1, (uint32_t)((kt + 1) & 1) * VSZ);
                CP_COMMIT;
            }
            const uint32_t base = (uint32_t)(kt & 1) * VSZ;

            // A fragments: direct LDG (L2-hot, coalesced 512B per warp)
            uint4 af[8];
            #pragma unroll
            for (int ks = 0; ks < 8; ks++)
                af[ks] = pw[(size_t)(kt * 8 + ks) * 32 + l];

            // MMAs
            #pragma unroll
            for (int ks = 0; ks < 8; ks++) {
                const uint32_t* a = (const uint32_t*)&af[ks];
                #pragma unroll
                for (int np = 0; np < 4; np++) {
                    int rowN = np * 16 + bro;
                    uint32_t off = (uint32_t)(rowN * RS2) * 2 + (bkc4 + ks * 16) * 2;
                    uint32_t vh4[4];
                    ldsm_x4(vh4, sb + base + off);
                    mma16816h(oacc[2 * np],     a, vh4[0], vh4[1]);
                    mma16816h(oacc[2 * np + 1], a, vh4[2], vh4[3]);
                }
            }

            // attn stores straight from the fragments
            #pragma unroll
            for (int ks = 0; ks < 8; ks++) {
                const uint32_t* a = (const uint32_t*)&af[ks];
                float2 f0 = __half22float2(*(const __half2*)&a[0]);
                float2 f1 = __half22float2(*(const __half2*)&a[1]);
                float2 f2 = __half22float2(*(const __half2*)&a[2]);
                float2 f3 = __half22float2(*(const __half2*)&a[3]);
                int c0 = kt * 128 + ks * 16 + q2;
                stcs2(&arow[(size_t)r0 * SEQ + c0],           make_float2(f0.x * iv0, f0.y * iv0));
                stcs2(&arow[(size_t)(r0 + 8) * SEQ + c0],     make_float2(f1.x * iv1, f1.y * iv1));
                stcs2(&arow[(size_t)r0 * SEQ + c0 + 8],       make_float2(f2.x * iv0, f2.y * iv0));
                stcs2(&arow[(size_t)(r0 + 8) * SEQ + c0 + 8], make_float2(f3.x * iv1, f3.y * iv1));
            }

            if (kt + 1 < 16) CP_WAIT0;
            __syncthreads();
        }

        float* ob = out + ((size_t)bh * SEQ + m0) * DIM;
        #pragma unroll
        for (int np = 0; np < 8; np++) {
            int col = np * 8 + q2;
            *(float2*)&ob[(size_t)r0 * DIM + col] =
                make_float2(oacc[np][0] * iv0, oacc[np][1] * iv0);
            *(float2*)&ob[(size_t)(r0 + 8) * DIM + col] =
                make_float2(oacc[np][2] * iv1, oacc[np][3] * iv1);
        }
    }
}

// ---------------- launch ----------------
extern "C" void kernel_launch(void* const* d_in, const int* in_sizes, int n_in,
                              void* d_out, int out_size) {
    const float* Q    = (const float*)d_in[0];
    const float* K    = (const float*)d_in[1];
    const float* V    = (const float*)d_in[2];
    const int*   mask = (const int*)d_in[3];

    float* out  = (float*)d_out;                      // [B,H,S,D]
    float* attn = out + (size_t)NBH * SEQ * DIM;      // [B,H,S,S]

    constexpr int STRIP_SMEM = 110592;
    cudaFuncSetAttribute(fused_strip, cudaFuncAttributeMaxDynamicSharedMemorySize, STRIP_SMEM);

    mask_compress<<<SEQ * (SEQ / 32) / 256, 256>>>(mask);

    dim3 gs((unsigned)((size_t)NBH * SEQ * DIM / 4 / 256), 2);
    split_prep2<<<gs, 256>>>(Q, K);

    dim3 g0(SEQ / 128, NBH);
    vt_prep<<<g0, 256>>>(V);

    dim3 g1(SEQ / 128, NBH);
    fused_strip<<<g1, 256, STRIP_SMEM>>>(attn, out);
}